// round 3
// baseline (speedup 1.0000x reference)
#include <cuda_runtime.h>
#include <math_constants.h>

// ---------------------------------------------------------------------------
// RVQBottleneck: 2-stage residual VQ.
//   out[r] = emb0[argmin_j ||x_r - e0_j||^2] + emb1[argmin_j ||res_r - e1_j||^2]
// Distances replicate the reference expression tree exactly:
//   dist = fl( fl(x2 + e2) - 2*xe ),  argmin with first-index tie break.
// Round 3: GEMM inner loop on the packed-FP32 path (fma.rn.f32x2) -> 2 FMA
// lanes per issue slot. Each lane is standard RN fp32 FMA, accumulation order
// per output element unchanged -> bit-identical to the round-2 kernel
// (which matched the reference at rel_err 0.0).
// ---------------------------------------------------------------------------

#define D        512
#define MAXROWS  32768
#define NCMAX    1024

#define BM 128
#define BN 128
#define BK 16
#define SMLD_A 260   // 2*BM + 4 pad (1040 B row: 16B-aligned, bank-skewed)
#define SMLD_B 132   // BM + 4 pad   (528 B row: 16B-aligned)

// Scratch (allocation-free: __device__ globals)
__device__ float g_resid[(size_t)MAXROWS * D];
__device__ float g_x2[MAXROWS];
__device__ float g_r2[MAXROWS];
__device__ float g_e2a[NCMAX];
__device__ float g_e2b[NCMAX];
__device__ int   g_idx0[MAXROWS];
__device__ int   g_idx1[MAXROWS];

__device__ __forceinline__ void fma2(unsigned long long& acc,
                                     unsigned long long a,
                                     unsigned long long b)
{
    asm("fma.rn.f32x2 %0, %1, %2, %0;" : "+l"(acc) : "l"(a), "l"(b));
}

__device__ __forceinline__ float lo32f(unsigned long long v)
{
    return __int_as_float((int)(unsigned)(v & 0xFFFFFFFFull));
}
__device__ __forceinline__ float hi32f(unsigned long long v)
{
    return __int_as_float((int)(unsigned)(v >> 32));
}

// ---------------------------------------------------------------------------
// Row squared-norm: one warp per row (D=512 -> 4 float4 per lane).
// ---------------------------------------------------------------------------
__global__ void rownorm_kernel(const float* __restrict__ src,
                               float* __restrict__ dst, int nrows)
{
    int row  = blockIdx.x * 8 + (threadIdx.x >> 5);
    if (row >= nrows) return;
    int lane = threadIdx.x & 31;
    const float4* p = (const float4*)(src + (size_t)row * D);
    float s = 0.f;
#pragma unroll
    for (int i = 0; i < D / 128; i++) {
        float4 v = p[lane + 32 * i];
        s += v.x * v.x + v.y * v.y + v.z * v.z + v.w * v.w;
    }
#pragma unroll
    for (int o = 16; o; o >>= 1) s += __shfl_down_sync(0xFFFFFFFFu, s, o);
    if (lane == 0) dst[row] = s;
}

// ---------------------------------------------------------------------------
// Fused GEMM + argmin stage (packed f32x2 microkernel).
// Block: 256 threads = 16x16; tile BM(128 rows) x BN(128 cols), loops over all
// ncodes columns so the argmin is block-local. 8x8 microtile per thread,
// held as 8x4 packed f32x2 accumulators.
// ---------------------------------------------------------------------------
__global__ __launch_bounds__(256, 2)
void stage_kernel(const float* __restrict__ X, const float* __restrict__ E,
                  const float* __restrict__ rn2, const float* __restrict__ en2,
                  int* __restrict__ outIdx, int ncodes)
{
    // As2 holds the X tile with every value duplicated: As2[k][2r]=As2[k][2r+1]=x
    // so a ld.shared.v2.f32-pair is directly an (a,a) f32x2 operand.
    __shared__ float As2[BK][SMLD_A];
    __shared__ float Bs [BK][SMLD_B];

    const int tid = threadIdx.x;
    const int tx  = tid & 15;      // column group
    const int ty  = tid >> 4;      // row group
    const int rowBase = blockIdx.x * BM;

    float myx2[8];
#pragma unroll
    for (int i = 0; i < 8; i++) myx2[i] = __ldg(&rn2[rowBase + ty * 8 + i]);

    float bestd[8];
    int   besti[8];
#pragma unroll
    for (int i = 0; i < 8; i++) { bestd[i] = CUDART_INF_F; besti[i] = 0; }

    for (int colBase = 0; colBase < ncodes; colBase += BN) {
        unsigned long long acc[8][4];
#pragma unroll
        for (int i = 0; i < 8; i++)
#pragma unroll
            for (int j = 0; j < 4; j++) acc[i][j] = 0ull;

        for (int kBase = 0; kBase < D; kBase += BK) {
            // Cooperative load: 128x16 tiles of X (duplicated) and E.
#pragma unroll
            for (int l = 0; l < 2; l++) {
                int f  = tid + 256 * l;      // float4 index 0..511
                int r  = f >> 2;             // tile row 0..127
                int kc = (f & 3) << 2;       // k offset 0,4,8,12
                float4 v = *(const float4*)(X + (size_t)(rowBase + r) * D + kBase + kc);
                *(float2*)&As2[kc + 0][2 * r] = make_float2(v.x, v.x);
                *(float2*)&As2[kc + 1][2 * r] = make_float2(v.y, v.y);
                *(float2*)&As2[kc + 2][2 * r] = make_float2(v.z, v.z);
                *(float2*)&As2[kc + 3][2 * r] = make_float2(v.w, v.w);
                float4 w = *(const float4*)(E + (size_t)(colBase + r) * D + kBase + kc);
                Bs[kc + 0][r] = w.x; Bs[kc + 1][r] = w.y;
                Bs[kc + 2][r] = w.z; Bs[kc + 3][r] = w.w;
            }
            __syncthreads();

#pragma unroll
            for (int k = 0; k < BK; k++) {
                // a-pairs: (a0,a0)..(a7,a7) from duplicated smem, 4 x LDS.128
                ulonglong2 av0 = *(const ulonglong2*)&As2[k][ty * 16 + 0];
                ulonglong2 av1 = *(const ulonglong2*)&As2[k][ty * 16 + 4];
                ulonglong2 av2 = *(const ulonglong2*)&As2[k][ty * 16 + 8];
                ulonglong2 av3 = *(const ulonglong2*)&As2[k][ty * 16 + 12];
                // b-pairs: (b0,b1)..(b6,b7), 2 x LDS.128
                ulonglong2 bv0 = *(const ulonglong2*)&Bs[k][tx * 8 + 0];
                ulonglong2 bv1 = *(const ulonglong2*)&Bs[k][tx * 8 + 4];

                unsigned long long ap[8] = { av0.x, av0.y, av1.x, av1.y,
                                             av2.x, av2.y, av3.x, av3.y };
                unsigned long long bp[4] = { bv0.x, bv0.y, bv1.x, bv1.y };
#pragma unroll
                for (int i = 0; i < 8; i++) {
                    fma2(acc[i][0], ap[i], bp[0]);
                    fma2(acc[i][1], ap[i], bp[1]);
                    fma2(acc[i][2], ap[i], bp[2]);
                    fma2(acc[i][3], ap[i], bp[3]);
                }
            }
            __syncthreads();
        }

        // Epilogue: dist = fl(fl(x2+e2) - 2*xe), track (min, first index).
#pragma unroll
        for (int jp = 0; jp < 4; jp++) {
            int col0 = colBase + tx * 8 + 2 * jp;
            float e20 = __ldg(&en2[col0]);
            float e21 = __ldg(&en2[col0 + 1]);
#pragma unroll
            for (int i = 0; i < 8; i++) {
                float xe0 = lo32f(acc[i][jp]);
                float xe1 = hi32f(acc[i][jp]);
                float t0  = __fadd_rn(myx2[i], e20);
                float d0  = __fmaf_rn(-2.0f, xe0, t0);
                if (d0 < bestd[i] || (d0 == bestd[i] && col0 < besti[i])) {
                    bestd[i] = d0; besti[i] = col0;
                }
                float t1  = __fadd_rn(myx2[i], e21);
                float d1  = __fmaf_rn(-2.0f, xe1, t1);
                if (d1 < bestd[i] || (d1 == bestd[i] && col0 + 1 < besti[i])) {
                    bestd[i] = d1; besti[i] = col0 + 1;
                }
            }
        }
    }

    // Reduce the 16 column-group lanes (same ty, consecutive lanes) per row.
#pragma unroll
    for (int i = 0; i < 8; i++) {
        float d  = bestd[i];
        int   ix = besti[i];
#pragma unroll
        for (int o = 8; o; o >>= 1) {
            float od = __shfl_down_sync(0xFFFFFFFFu, d,  o, 16);
            int   oi = __shfl_down_sync(0xFFFFFFFFu, ix, o, 16);
            if (od < d || (od == d && oi < ix)) { d = od; ix = oi; }
        }
        if (tx == 0) outIdx[rowBase + ty * 8 + i] = ix;
    }
}

// ---------------------------------------------------------------------------
// Residual: R[r] = X[r] - E[idx[r]] (exact fp32, same as ref) + fused ||R||^2.
// ---------------------------------------------------------------------------
__global__ void resid_kernel(const float* __restrict__ X, const float* __restrict__ E,
                             const int* __restrict__ idx, float* __restrict__ R,
                             float* __restrict__ r2)
{
    int row = blockIdx.x;
    int t   = threadIdx.x;     // 0..127
    int c   = idx[row];
    float4 xv = ((const float4*)(X + (size_t)row * D))[t];
    float4 ev = ((const float4*)(E + (size_t)c   * D))[t];
    float4 rv = make_float4(xv.x - ev.x, xv.y - ev.y, xv.z - ev.z, xv.w - ev.w);
    ((float4*)(R + (size_t)row * D))[t] = rv;

    float s = rv.x * rv.x + rv.y * rv.y + rv.z * rv.z + rv.w * rv.w;
#pragma unroll
    for (int o = 16; o; o >>= 1) s += __shfl_down_sync(0xFFFFFFFFu, s, o);
    __shared__ float red[4];
    if ((t & 31) == 0) red[t >> 5] = s;
    __syncthreads();
    if (t == 0) r2[row] = red[0] + red[1] + red[2] + red[3];
}

// ---------------------------------------------------------------------------
// Output: out = fl(x + fl(fl(e0+e1) - x))  (replicates reference STE rounding)
// ---------------------------------------------------------------------------
__global__ void out_kernel(const float* __restrict__ X, const float* __restrict__ E0,
                           const float* __restrict__ E1, const int* __restrict__ i0,
                           const int* __restrict__ i1, float* __restrict__ out)
{
    int row = blockIdx.x;
    int t   = threadIdx.x;     // 0..127
    int c0  = i0[row];
    int c1  = i1[row];
    float4 xv = ((const float4*)(X  + (size_t)row * D))[t];
    float4 a  = ((const float4*)(E0 + (size_t)c0  * D))[t];
    float4 b  = ((const float4*)(E1 + (size_t)c1  * D))[t];
    float4 o;
    o.x = __fadd_rn(xv.x, __fadd_rn(__fadd_rn(a.x, b.x), -xv.x));
    o.y = __fadd_rn(xv.y, __fadd_rn(__fadd_rn(a.y, b.y), -xv.y));
    o.z = __fadd_rn(xv.z, __fadd_rn(__fadd_rn(a.z, b.z), -xv.z));
    o.w = __fadd_rn(xv.w, __fadd_rn(__fadd_rn(a.w, b.w), -xv.w));
    ((float4*)(out + (size_t)row * D))[t] = o;
}

// ---------------------------------------------------------------------------
extern "C" void kernel_launch(void* const* d_in, const int* in_sizes, int n_in,
                              void* d_out, int out_size)
{
    const float* x  = (const float*)d_in[0];
    const float* e0 = (const float*)d_in[1];
    const float* e1 = (const float*)d_in[2];
    float* out = (float*)d_out;

    int rows = in_sizes[0] / D;   // 32768
    int nc   = in_sizes[1] / D;   // 1024

    float *px2, *pr2, *pe2a, *pe2b, *pres;
    int   *pi0, *pi1;
    cudaGetSymbolAddress((void**)&px2,  g_x2);
    cudaGetSymbolAddress((void**)&pr2,  g_r2);
    cudaGetSymbolAddress((void**)&pe2a, g_e2a);
    cudaGetSymbolAddress((void**)&pe2b, g_e2b);
    cudaGetSymbolAddress((void**)&pres, g_resid);
    cudaGetSymbolAddress((void**)&pi0,  g_idx0);
    cudaGetSymbolAddress((void**)&pi1,  g_idx1);

    rownorm_kernel<<<(rows + 7) / 8, 256>>>(x,  px2,  rows);
    rownorm_kernel<<<(nc   + 7) / 8, 256>>>(e0, pe2a, nc);
    rownorm_kernel<<<(nc   + 7) / 8, 256>>>(e1, pe2b, nc);

    stage_kernel<<<rows / BM, 256>>>(x, e0, px2, pe2a, pi0, nc);
    resid_kernel<<<rows, 128>>>(x, e0, pi0, pres, pr2);
    stage_kernel<<<rows / BM, 256>>>(pres, e1, pr2, pe2b, pi1, nc);
    out_kernel<<<rows, 128>>>(x, e0, e1, pi0, pi1, out);
}

// round 6
// speedup vs baseline: 1.3460x; 1.3460x over previous
#include <cuda_runtime.h>
#include <math_constants.h>
#include <cstdint>

// ---------------------------------------------------------------------------
// RVQBottleneck: 2-stage residual VQ, tensor-core path via mma.sync tf32
// (sm_100 plain target: tcgen05 is NOT available in this build).
//   dist = fl( fl(x2 + e2) - 2*xe ), argmin first-index tie break.
//   xe ~= hi*hi + hi*lo + lo*hi  (tf32 3-way split, fp32 accumulate).
// Near-ties (top2 within MARGIN) are exactly rescored in fp32.
// ---------------------------------------------------------------------------

#define D        512
#define MAXROWS  32768
#define NCMAX    1024

#define BM   128
#define BK   16
#define SA   20            // smem row stride (floats): bank=(4r+c)%32 all-distinct
#define MAT_F   (BM * SA)          // 2560 floats per matrix tile
#define STAGE_F (4 * MAT_F)        // Ahi Alo Bhi Blo = 10240 floats
#define SMEM_FLOATS (2 * STAGE_F + 4 * 256)   // 2 stages + top2 red arrays
#define SMEM_BYTES  (SMEM_FLOATS * 4)         // 86016

#define MARGIN 2.5e-4f

// ---- scratch (allocation-free) --------------------------------------------
__device__ float g_ahi[(size_t)MAXROWS * D];
__device__ float g_alo[(size_t)MAXROWS * D];
__device__ float g_res[(size_t)MAXROWS * D];
__device__ float g_e0hi[(size_t)NCMAX * D];
__device__ float g_e0lo[(size_t)NCMAX * D];
__device__ float g_e1hi[(size_t)NCMAX * D];
__device__ float g_e1lo[(size_t)NCMAX * D];
__device__ float g_x2[MAXROWS];
__device__ float g_r2[MAXROWS];
__device__ float g_e2a[NCMAX];
__device__ float g_e2b[NCMAX];
__device__ int   g_idx0[MAXROWS];
__device__ int   g_idx1[MAXROWS];

// ---- helpers --------------------------------------------------------------
__device__ __forceinline__ float tf32r(float x) {
    uint32_t r;
    asm("cvt.rna.tf32.f32 %0, %1;" : "=r"(r) : "f"(x));
    return __uint_as_float(r);
}
#define CPASYNC16(dst, src) \
    asm volatile("cp.async.cg.shared.global [%0], [%1], 16;" :: "r"(dst), "l"(src) : "memory")
#define CPCOMMIT() asm volatile("cp.async.commit_group;" ::: "memory")
#define CPWAIT(n)  asm volatile("cp.async.wait_group %0;" :: "n"(n) : "memory")

#define MMA_TF32(d, a, b0, b1) \
    asm volatile("mma.sync.aligned.m16n8k8.row.col.f32.tf32.tf32.f32 " \
        "{%0,%1,%2,%3}, {%4,%5,%6,%7}, {%8,%9}, {%0,%1,%2,%3};" \
        : "+f"((d)[0]), "+f"((d)[1]), "+f"((d)[2]), "+f"((d)[3]) \
        : "r"((a)[0]), "r"((a)[1]), "r"((a)[2]), "r"((a)[3]), "r"(b0), "r"(b1))

__device__ __forceinline__ bool betterf(float d, int i, float rd, int ri) {
    return d < rd || (d == rd && i < ri);
}

__device__ __forceinline__ uint32_t smem_u32_of(const void* p) {
    uint32_t a;
    asm("{ .reg .u64 t; cvta.to.shared.u64 t, %1; cvt.u32.u64 %0, t; }"
        : "=r"(a) : "l"(p));
    return a;
}

// ---------------------------------------------------------------------------
// tf32 split: hi = tf32(x), lo = tf32(x - hi).
// ---------------------------------------------------------------------------
__global__ void split_kernel(const float* __restrict__ src,
                             float* __restrict__ hi, float* __restrict__ lo, int n4)
{
    int i = blockIdx.x * blockDim.x + threadIdx.x;
    if (i >= n4) return;
    float4 v = ((const float4*)src)[i];
    float4 h, l;
    h.x = tf32r(v.x); l.x = tf32r(v.x - h.x);
    h.y = tf32r(v.y); l.y = tf32r(v.y - h.y);
    h.z = tf32r(v.z); l.z = tf32r(v.z - h.z);
    h.w = tf32r(v.w); l.w = tf32r(v.w - h.w);
    ((float4*)hi)[i] = h;
    ((float4*)lo)[i] = l;
}

// ---------------------------------------------------------------------------
// Row squared-norm (same as the bit-exact round-2 kernel).
// ---------------------------------------------------------------------------
__global__ void rownorm_kernel(const float* __restrict__ src,
                               float* __restrict__ dst, int nrows)
{
    int row  = blockIdx.x * 8 + (threadIdx.x >> 5);
    if (row >= nrows) return;
    int lane = threadIdx.x & 31;
    const float4* p = (const float4*)(src + (size_t)row * D);
    float s = 0.f;
#pragma unroll
    for (int i = 0; i < D / 128; i++) {
        float4 v = p[lane + 32 * i];
        s += v.x * v.x + v.y * v.y + v.z * v.z + v.w * v.w;
    }
#pragma unroll
    for (int o = 16; o; o >>= 1) s += __shfl_down_sync(0xFFFFFFFFu, s, o);
    if (lane == 0) dst[row] = s;
}

// ---------------------------------------------------------------------------
// Fused tensor-core GEMM + argmin stage.
// Block 256 thr (8 warps, 4x2 warp grid; warp tile 32x64). Tile 128 rows x
// all ncodes cols (col-tiles of 128). BK=16, cp.async double buffered.
// ---------------------------------------------------------------------------
__global__ __launch_bounds__(256, 2)
void stage_mma_kernel(const float* __restrict__ Ahi, const float* __restrict__ Alo,
                      const float* __restrict__ Bhi, const float* __restrict__ Blo,
                      const float* __restrict__ Xex, const float* __restrict__ Eex,
                      const float* __restrict__ rn2, const float* __restrict__ en2,
                      int* __restrict__ outIdx, int ncodes)
{
    extern __shared__ float smf[];
    const uint32_t smb = smem_u32_of(smf);

    const int tid  = threadIdx.x;
    const int lane = tid & 31;
    const int wid  = tid >> 5;
    const int wm   = wid & 3;        // warp row group (32 rows)
    const int wn   = wid >> 2;       // warp col group (64 cols)
    const int gid  = lane >> 2;      // 0..7
    const int tig  = lane & 3;       // 0..3
    const int rowBase = blockIdx.x * BM;

    // row slots: s = mtile*2 + half -> row = wm*32 + mtile*16 + half*8 + gid
    float myx2[4];
#pragma unroll
    for (int s = 0; s < 4; ++s)
        myx2[s] = __ldg(&rn2[rowBase + wm * 32 + (s >> 1) * 16 + (s & 1) * 8 + gid]);

    float b1d[4], b2d[4];
    int   b1i[4], b2i[4];
#pragma unroll
    for (int s = 0; s < 4; ++s) {
        b1d[s] = CUDART_INF_F; b1i[s] = 0x7FFFFFFF;
        b2d[s] = CUDART_INF_F; b2i[s] = 0x7FFFFFFF;
    }

    float acc[2][8][4];

    const int NCT = ncodes >> 7;        // col-tiles of 128
    const int NG  = NCT * 32;           // 32 k-chunks per col-tile

    for (int G = 0; G < NG; ++G) {
        // ---- async loads (chunk G+1 into other buffer) ----
        if (G == 0) {
            // issue chunk 0
            const int kB = 0, cB = 0;
            const uint32_t sbase = smb;
#pragma unroll
            for (int m = 0; m < 2; ++m) {
                int idx = tid + 256 * m, r = idx >> 2, c4 = idx & 3;
                uint32_t doff = (uint32_t)(r * SA + c4 * 4) * 4;
                CPASYNC16(sbase + doff,               Ahi + (size_t)(rowBase + r) * D + kB + c4 * 4);
                CPASYNC16(sbase + MAT_F*4 + doff,     Alo + (size_t)(rowBase + r) * D + kB + c4 * 4);
                CPASYNC16(sbase + 2*MAT_F*4 + doff,   Bhi + (size_t)(cB + r) * D + kB + c4 * 4);
                CPASYNC16(sbase + 3*MAT_F*4 + doff,   Blo + (size_t)(cB + r) * D + kB + c4 * 4);
            }
            CPCOMMIT();
        }
        if (G + 1 < NG) {
            const int g1 = G + 1;
            const int kB = (g1 & 31) * BK, cB = (g1 >> 5) * 128;
            const uint32_t sbase = smb + (uint32_t)(g1 & 1) * STAGE_F * 4;
#pragma unroll
            for (int m = 0; m < 2; ++m) {
                int idx = tid + 256 * m, r = idx >> 2, c4 = idx & 3;
                uint32_t doff = (uint32_t)(r * SA + c4 * 4) * 4;
                CPASYNC16(sbase + doff,               Ahi + (size_t)(rowBase + r) * D + kB + c4 * 4);
                CPASYNC16(sbase + MAT_F*4 + doff,     Alo + (size_t)(rowBase + r) * D + kB + c4 * 4);
                CPASYNC16(sbase + 2*MAT_F*4 + doff,   Bhi + (size_t)(cB + r) * D + kB + c4 * 4);
                CPASYNC16(sbase + 3*MAT_F*4 + doff,   Blo + (size_t)(cB + r) * D + kB + c4 * 4);
            }
            CPCOMMIT();
            CPWAIT(1);
        } else {
            CPWAIT(0);
        }
        __syncthreads();

        if ((G & 31) == 0) {
#pragma unroll
            for (int mt = 0; mt < 2; ++mt)
#pragma unroll
                for (int nt = 0; nt < 8; ++nt)
#pragma unroll
                    for (int c = 0; c < 4; ++c) acc[mt][nt][c] = 0.f;
        }

        // ---- compute on buffer G&1 ----
        {
            const float* S  = smf + (G & 1) * STAGE_F;
            const float* A0 = S;
            const float* A1 = S + MAT_F;
            const float* B0 = S + 2 * MAT_F;
            const float* B1 = S + 3 * MAT_F;
#pragma unroll
            for (int ks = 0; ks < 2; ++ks) {
                const int kc = ks * 8 + tig;
                uint32_t ah[2][4], al[2][4];
#pragma unroll
                for (int mt = 0; mt < 2; ++mt) {
                    const int r = wm * 32 + mt * 16 + gid;
                    ah[mt][0] = __float_as_uint(A0[r * SA + kc]);
                    ah[mt][1] = __float_as_uint(A0[(r + 8) * SA + kc]);
                    ah[mt][2] = __float_as_uint(A0[r * SA + kc + 4]);
                    ah[mt][3] = __float_as_uint(A0[(r + 8) * SA + kc + 4]);
                    al[mt][0] = __float_as_uint(A1[r * SA + kc]);
                    al[mt][1] = __float_as_uint(A1[(r + 8) * SA + kc]);
                    al[mt][2] = __float_as_uint(A1[r * SA + kc + 4]);
                    al[mt][3] = __float_as_uint(A1[(r + 8) * SA + kc + 4]);
                }
#pragma unroll
                for (int nt = 0; nt < 8; ++nt) {
                    const int cr = wn * 64 + nt * 8 + gid;
                    uint32_t bh0 = __float_as_uint(B0[cr * SA + kc]);
                    uint32_t bh1 = __float_as_uint(B0[cr * SA + kc + 4]);
                    uint32_t bl0 = __float_as_uint(B1[cr * SA + kc]);
                    uint32_t bl1 = __float_as_uint(B1[cr * SA + kc + 4]);
#pragma unroll
                    for (int mt = 0; mt < 2; ++mt) {
                        MMA_TF32(acc[mt][nt], ah[mt], bh0, bh1);
                        MMA_TF32(acc[mt][nt], ah[mt], bl0, bl1);
                        MMA_TF32(acc[mt][nt], al[mt], bh0, bh1);
                    }
                }
            }
        }
        __syncthreads();

        // ---- epilogue once per col-tile ----
        if ((G & 31) == 31) {
            const int ct = G >> 5;
#pragma unroll
            for (int mt = 0; mt < 2; ++mt)
#pragma unroll
                for (int nt = 0; nt < 8; ++nt)
#pragma unroll
                    for (int c = 0; c < 4; ++c) {
                        const int col = ct * 128 + wn * 64 + nt * 8 + tig * 2 + (c & 1);
                        const int s   = mt * 2 + (c >> 1);
                        float e2 = __ldg(&en2[col]);
                        float t  = __fadd_rn(myx2[s], e2);
                        float dd = __fmaf_rn(-2.0f, acc[mt][nt][c], t);
                        if (betterf(dd, col, b1d[s], b1i[s])) {
                            b2d[s] = b1d[s]; b2i[s] = b1i[s];
                            b1d[s] = dd;     b1i[s] = col;
                        } else if (betterf(dd, col, b2d[s], b2i[s])) {
                            b2d[s] = dd;     b2i[s] = col;
                        }
                    }
        }
    }

    // ---- top2 reduction: across tig (shfl), then across warp_n (smem) ----
    float* sd1 = smf + 2 * STAGE_F;
    int*   si1 = (int*)(sd1 + 256);
    float* sd2 = (float*)(si1 + 256);
    int*   si2 = (int*)(sd2 + 256);

#pragma unroll
    for (int s = 0; s < 4; ++s) {
        float d1 = b1d[s], d2 = b2d[s];
        int   i1 = b1i[s], i2 = b2i[s];
#pragma unroll
        for (int off = 1; off < 4; off <<= 1) {
            float pd1 = __shfl_xor_sync(0xFFFFFFFFu, d1, off);
            int   pi1 = __shfl_xor_sync(0xFFFFFFFFu, i1, off);
            float pd2 = __shfl_xor_sync(0xFFFFFFFFu, d2, off);
            int   pi2 = __shfl_xor_sync(0xFFFFFFFFu, i2, off);
            if (betterf(pd1, pi1, d1, i1)) {
                if (betterf(d1, i1, pd2, pi2)) { d2 = d1; i2 = i1; }
                else                           { d2 = pd2; i2 = pi2; }
                d1 = pd1; i1 = pi1;
            } else if (betterf(pd1, pi1, d2, i2)) {
                d2 = pd1; i2 = pi1;
            }
        }
        if (tig == 0) {
            const int row = wm * 32 + (s >> 1) * 16 + (s & 1) * 8 + gid;
            sd1[wn * 128 + row] = d1;  si1[wn * 128 + row] = i1;
            sd2[wn * 128 + row] = d2;  si2[wn * 128 + row] = i2;
        }
    }
    __syncthreads();

    if (tid < 128) {
        float d1 = sd1[tid], d2 = sd2[tid];
        int   i1 = si1[tid], i2 = si2[tid];
        {
            float pd1 = sd1[128 + tid], pd2 = sd2[128 + tid];
            int   pi1 = si1[128 + tid], pi2 = si2[128 + tid];
            if (betterf(pd1, pi1, d1, i1)) {
                if (betterf(d1, i1, pd2, pi2)) { d2 = d1; i2 = i1; }
                else                           { d2 = pd2; i2 = pi2; }
                d1 = pd1; i1 = pi1;
            } else if (betterf(pd1, pi1, d2, i2)) {
                d2 = pd1; i2 = pi1;
            }
        }
        int winner = i1;
        if (d2 - d1 <= MARGIN) {
            // exact fp32 rescore of the near-tied pair, reference semantics
            int ia = min(i1, i2), ib = max(i1, i2);
            const float* xr = Xex + (size_t)(rowBase + tid) * D;
            float x2v = __ldg(&rn2[rowBase + tid]);
            const float* ea = Eex + (size_t)ia * D;
            const float* eb = Eex + (size_t)ib * D;
            float xea = 0.f, xeb = 0.f;
            for (int k = 0; k < D; ++k) {
                float xv = __ldg(&xr[k]);
                xea = __fmaf_rn(xv, __ldg(&ea[k]), xea);
                xeb = __fmaf_rn(xv, __ldg(&eb[k]), xeb);
            }
            float da = __fmaf_rn(-2.f, xea, __fadd_rn(x2v, __ldg(&en2[ia])));
            float db = __fmaf_rn(-2.f, xeb, __fadd_rn(x2v, __ldg(&en2[ib])));
            winner = (db < da) ? ib : ia;   // tie -> lower index ia
        }
        outIdx[rowBase + tid] = winner;
    }
}

// ---------------------------------------------------------------------------
// Residual (exact fp32, matches reference) + exact copy + tf32 split + ||R||^2.
// ---------------------------------------------------------------------------
__global__ void resid_split_kernel(const float* __restrict__ X,
                                   const float* __restrict__ E,
                                   const int* __restrict__ idx,
                                   float* __restrict__ Rex,
                                   float* __restrict__ Rhi, float* __restrict__ Rlo,
                                   float* __restrict__ r2)
{
    int row = blockIdx.x;
    int t   = threadIdx.x;     // 0..127
    int c   = idx[row];
    float4 xv = ((const float4*)(X + (size_t)row * D))[t];
    float4 ev = ((const float4*)(E + (size_t)c   * D))[t];
    float4 rv = make_float4(xv.x - ev.x, xv.y - ev.y, xv.z - ev.z, xv.w - ev.w);
    ((float4*)(Rex + (size_t)row * D))[t] = rv;
    float4 h, l;
    h.x = tf32r(rv.x); l.x = tf32r(rv.x - h.x);
    h.y = tf32r(rv.y); l.y = tf32r(rv.y - h.y);
    h.z = tf32r(rv.z); l.z = tf32r(rv.z - h.z);
    h.w = tf32r(rv.w); l.w = tf32r(rv.w - h.w);
    ((float4*)(Rhi + (size_t)row * D))[t] = h;
    ((float4*)(Rlo + (size_t)row * D))[t] = l;

    float s = rv.x * rv.x + rv.y * rv.y + rv.z * rv.z + rv.w * rv.w;
#pragma unroll
    for (int o = 16; o; o >>= 1) s += __shfl_down_sync(0xFFFFFFFFu, s, o);
    __shared__ float red[4];
    if ((t & 31) == 0) red[t >> 5] = s;
    __syncthreads();
    if (t == 0) r2[row] = red[0] + red[1] + red[2] + red[3];
}

// ---------------------------------------------------------------------------
// Output: out = fl(x + fl(fl(e0+e1) - x))  (reference STE rounding)
// ---------------------------------------------------------------------------
__global__ void out_kernel(const float* __restrict__ X, const float* __restrict__ E0,
                           const float* __restrict__ E1, const int* __restrict__ i0,
                           const int* __restrict__ i1, float* __restrict__ out)
{
    int row = blockIdx.x;
    int t   = threadIdx.x;     // 0..127
    int c0  = i0[row];
    int c1  = i1[row];
    float4 xv = ((const float4*)(X  + (size_t)row * D))[t];
    float4 a  = ((const float4*)(E0 + (size_t)c0  * D))[t];
    float4 b  = ((const float4*)(E1 + (size_t)c1  * D))[t];
    float4 o;
    o.x = __fadd_rn(xv.x, __fadd_rn(__fadd_rn(a.x, b.x), -xv.x));
    o.y = __fadd_rn(xv.y, __fadd_rn(__fadd_rn(a.y, b.y), -xv.y));
    o.z = __fadd_rn(xv.z, __fadd_rn(__fadd_rn(a.z, b.z), -xv.z));
    o.w = __fadd_rn(xv.w, __fadd_rn(__fadd_rn(a.w, b.w), -xv.w));
    ((float4*)(out + (size_t)row * D))[t] = o;
}

// ---------------------------------------------------------------------------
extern "C" void kernel_launch(void* const* d_in, const int* in_sizes, int n_in,
                              void* d_out, int out_size)
{
    const float* x  = (const float*)d_in[0];
    const float* e0 = (const float*)d_in[1];
    const float* e1 = (const float*)d_in[2];
    float* out = (float*)d_out;

    int rows = in_sizes[0] / D;   // 32768
    int nc   = in_sizes[1] / D;   // 1024

    float *pahi, *palo, *pres, *pe0hi, *pe0lo, *pe1hi, *pe1lo;
    float *px2, *pr2, *pe2a, *pe2b;
    int   *pi0, *pi1;
    cudaGetSymbolAddress((void**)&pahi,  g_ahi);
    cudaGetSymbolAddress((void**)&palo,  g_alo);
    cudaGetSymbolAddress((void**)&pres,  g_res);
    cudaGetSymbolAddress((void**)&pe0hi, g_e0hi);
    cudaGetSymbolAddress((void**)&pe0lo, g_e0lo);
    cudaGetSymbolAddress((void**)&pe1hi, g_e1hi);
    cudaGetSymbolAddress((void**)&pe1lo, g_e1lo);
    cudaGetSymbolAddress((void**)&px2,   g_x2);
    cudaGetSymbolAddress((void**)&pr2,   g_r2);
    cudaGetSymbolAddress((void**)&pe2a,  g_e2a);
    cudaGetSymbolAddress((void**)&pe2b,  g_e2b);
    cudaGetSymbolAddress((void**)&pi0,   g_idx0);
    cudaGetSymbolAddress((void**)&pi1,   g_idx1);

    cudaFuncSetAttribute(stage_mma_kernel,
                         cudaFuncAttributeMaxDynamicSharedMemorySize, SMEM_BYTES);

    int n4x = rows * D / 4, n4e = nc * D / 4;
    split_kernel<<<(n4x + 255) / 256, 256>>>(x,  pahi,  palo,  n4x);
    split_kernel<<<(n4e + 255) / 256, 256>>>(e0, pe0hi, pe0lo, n4e);
    split_kernel<<<(n4e + 255) / 256, 256>>>(e1, pe1hi, pe1lo, n4e);

    rownorm_kernel<<<(rows + 7) / 8, 256>>>(x,  px2,  rows);
    rownorm_kernel<<<(nc   + 7) / 8, 256>>>(e0, pe2a, nc);
    rownorm_kernel<<<(nc   + 7) / 8, 256>>>(e1, pe2b, nc);

    stage_mma_kernel<<<rows / BM, 256, SMEM_BYTES>>>(pahi, palo, pe0hi, pe0lo,
                                                     x, e0, px2, pe2a, pi0, nc);
    resid_split_kernel<<<rows, 128>>>(x, e0, pi0, pres, pahi, palo, pr2);
    stage_mma_kernel<<<rows / BM, 256, SMEM_BYTES>>>(pahi, palo, pe1hi, pe1lo,
                                                     pres, e1, pr2, pe2b, pi1, nc);
    out_kernel<<<rows, 128>>>(x, e0, e1, pi0, pi1, out);
}

// round 7
// speedup vs baseline: 2.0124x; 1.4950x over previous
#include <cuda_runtime.h>
#include <cuda_bf16.h>
#include <math_constants.h>
#include <cstdint>

// ---------------------------------------------------------------------------
// RVQBottleneck: 2-stage residual VQ via mma.sync bf16 m16n8k16 3-term split.
//   dist = fl( fl(x2 + e2) - 2*xe ), argmin first-index tie break.
//   xe ~= h*h + h*m + m*h  where x = h + m + O(2^-18 x)  (bf16 two-level split)
// Near-ties (top2 within MARGIN) are exactly rescored in fp32.
// Packed scratch layout per row, per 16-k block (64B = 16 words):
//   word[t*4+0] = bf16x2(hi_{2t},  hi_{2t+1})
//   word[t*4+1] = bf16x2(mid_{2t}, mid_{2t+1})
//   word[t*4+2] = bf16x2(hi_{2t+8},  hi_{2t+9})
//   word[t*4+3] = bf16x2(mid_{2t+8}, mid_{2t+9})
// so one uint4 shared load = full hi+mid MMA fragments.
// ---------------------------------------------------------------------------

#define D        512
#define MAXROWS  32768
#define NCMAX    1024

#define BM   128
#define WPR  512            // packed words per row (D k-values, 1 word each)
#define MARGIN 2.5e-4f

// ---- scratch (allocation-free) --------------------------------------------
__device__ uint32_t g_apk[(size_t)MAXROWS * WPR];
__device__ uint32_t g_e0pk[(size_t)NCMAX * WPR];
__device__ uint32_t g_e1pk[(size_t)NCMAX * WPR];
__device__ float    g_res[(size_t)MAXROWS * D];
__device__ float    g_x2[MAXROWS];
__device__ float    g_r2[MAXROWS];
__device__ float    g_e2a[NCMAX];
__device__ float    g_e2b[NCMAX];
__device__ int      g_idx0[MAXROWS];
__device__ int      g_idx1[MAXROWS];

// ---- helpers --------------------------------------------------------------
__device__ __forceinline__ uint32_t bf16pack(float lo, float hi_) {
    uint32_t r;
    asm("cvt.rn.bf16x2.f32 %0, %1, %2;" : "=r"(r) : "f"(hi_), "f"(lo));
    return r;
}
__device__ __forceinline__ float bf16round(float x) {
    return __bfloat162float(__float2bfloat16(x));
}
#define CPASYNC16(dst, src) \
    asm volatile("cp.async.cg.shared.global [%0], [%1], 16;" :: "r"(dst), "l"(src) : "memory")
#define CPCOMMIT() asm volatile("cp.async.commit_group;" ::: "memory")
#define CPWAIT(n)  asm volatile("cp.async.wait_group %0;" :: "n"(n) : "memory")

#define MMA_BF16(d, a, b0, b1) \
    asm volatile("mma.sync.aligned.m16n8k16.row.col.f32.bf16.bf16.f32 " \
        "{%0,%1,%2,%3}, {%4,%5,%6,%7}, {%8,%9}, {%0,%1,%2,%3};" \
        : "+f"((d)[0]), "+f"((d)[1]), "+f"((d)[2]), "+f"((d)[3]) \
        : "r"((a)[0]), "r"((a)[1]), "r"((a)[2]), "r"((a)[3]), "r"(b0), "r"(b1))

__device__ __forceinline__ bool betterf(float d, int i, float rd, int ri) {
    return d < rd || (d == rd && i < ri);
}
__device__ __forceinline__ uint32_t smem_u32_of(const void* p) {
    uint32_t a;
    asm("{ .reg .u64 t; cvta.to.shared.u64 t, %1; cvt.u32.u64 %0, t; }"
        : "=r"(a) : "l"(p));
    return a;
}

// ---------------------------------------------------------------------------
// Pack: fp32 row-major -> interleaved bf16 hi/mid words (layout above).
// One thread per (row, 16k-block).
// ---------------------------------------------------------------------------
__global__ void pack_kernel(const float* __restrict__ src,
                            uint32_t* __restrict__ dst, int nrows)
{
    int i = blockIdx.x * blockDim.x + threadIdx.x;
    if (i >= nrows * 32) return;
    int row = i >> 5, blk = i & 31;
    const float4* s = (const float4*)(src + (size_t)row * D + blk * 16);
    float f[16];
    float4 F0 = s[0], F1 = s[1], F2 = s[2], F3 = s[3];
    f[0]=F0.x; f[1]=F0.y; f[2]=F0.z; f[3]=F0.w;
    f[4]=F1.x; f[5]=F1.y; f[6]=F1.z; f[7]=F1.w;
    f[8]=F2.x; f[9]=F2.y; f[10]=F2.z; f[11]=F2.w;
    f[12]=F3.x; f[13]=F3.y; f[14]=F3.z; f[15]=F3.w;
    uint4* d = (uint4*)(dst + (size_t)row * WPR + blk * 16);
#pragma unroll
    for (int t = 0; t < 4; ++t) {
        float x0 = f[2*t],     x1 = f[2*t+1];
        float x2 = f[2*t+8],   x3 = f[2*t+9];
        float m0 = x0 - bf16round(x0), m1 = x1 - bf16round(x1);
        float m2 = x2 - bf16round(x2), m3 = x3 - bf16round(x3);
        uint4 w;
        w.x = bf16pack(x0, x1);
        w.y = bf16pack(m0, m1);
        w.z = bf16pack(x2, x3);
        w.w = bf16pack(m2, m3);
        d[t] = w;
    }
}

// ---------------------------------------------------------------------------
// Row squared-norm (bit-exact, unchanged).
// ---------------------------------------------------------------------------
__global__ void rownorm_kernel(const float* __restrict__ src,
                               float* __restrict__ dst, int nrows)
{
    int row  = blockIdx.x * 8 + (threadIdx.x >> 5);
    if (row >= nrows) return;
    int lane = threadIdx.x & 31;
    const float4* p = (const float4*)(src + (size_t)row * D);
    float s = 0.f;
#pragma unroll
    for (int i = 0; i < D / 128; i++) {
        float4 v = p[lane + 32 * i];
        s += v.x * v.x + v.y * v.y + v.z * v.z + v.w * v.w;
    }
#pragma unroll
    for (int o = 16; o; o >>= 1) s += __shfl_down_sync(0xFFFFFFFFu, s, o);
    if (lane == 0) dst[row] = s;
}

// ---------------------------------------------------------------------------
// Fused bf16-MMA GEMM + argmin stage.
// 256 thr (8 warps, 4 row-groups x 2 col-groups; warp tile 32x64).
// Chunk = 16 k-values (one m16n8k16 sweep); 32 chunks per 128-col tile.
// ---------------------------------------------------------------------------
__global__ __launch_bounds__(256, 2)
void stage_mma_kernel(const uint32_t* __restrict__ Apk,
                      const uint32_t* __restrict__ Bpk,
                      const float* __restrict__ Xex, const float* __restrict__ Eex,
                      const float* __restrict__ rn2, const float* __restrict__ en2,
                      int* __restrict__ outIdx, int ncodes)
{
    __shared__ uint32_t Ab[2][2048];   // 8KB per buffer: 128 rows x 16 words
    __shared__ uint32_t Bb[2][2048];
    __shared__ float sd1[256]; __shared__ int si1[256];
    __shared__ float sd2[256]; __shared__ int si2[256];

    const uint32_t aB = smem_u32_of(Ab);
    const uint32_t bB = smem_u32_of(Bb);

    const int tid  = threadIdx.x;
    const int lane = tid & 31;
    const int wid  = tid >> 5;
    const int wm   = wid & 3;        // warp row group (32 rows)
    const int wn   = wid >> 2;       // warp col group (64 cols)
    const int gid  = lane >> 2;      // 0..7
    const int tig  = lane & 3;       // 0..3
    const int rowBase = blockIdx.x * BM;

    float myx2[4];
#pragma unroll
    for (int s = 0; s < 4; ++s)
        myx2[s] = __ldg(&rn2[rowBase + wm * 32 + (s >> 1) * 16 + (s & 1) * 8 + gid]);

    float b1d[4], b2d[4];
    int   b1i[4], b2i[4];
#pragma unroll
    for (int s = 0; s < 4; ++s) {
        b1d[s] = CUDART_INF_F; b1i[s] = 0x7FFFFFFF;
        b2d[s] = CUDART_INF_F; b2i[s] = 0x7FFFFFFF;
    }

    float acc[2][8][4];

    const int NCT = ncodes >> 7;
    const int NG  = NCT * 32;

    for (int G = 0; G < NG; ++G) {
        if (G == 0) {
#pragma unroll
            for (int m = 0; m < 2; ++m) {
                int j = tid + 256 * m, r = j >> 2, c = j & 3;
                CPASYNC16(aB + (uint32_t)(r * 16 + c * 4) * 4,
                          Apk + (size_t)(rowBase + r) * WPR + c * 4);
                CPASYNC16(bB + (uint32_t)(r * 16 + c * 4) * 4,
                          Bpk + (size_t)r * WPR + c * 4);
            }
            CPCOMMIT();
        }
        if (G + 1 < NG) {
            const int g1 = G + 1;
            const int kb = (g1 & 31) * 16, cB = (g1 >> 5) << 7;
            const uint32_t off = (uint32_t)(g1 & 1) * 8192u;
#pragma unroll
            for (int m = 0; m < 2; ++m) {
                int j = tid + 256 * m, r = j >> 2, c = j & 3;
                CPASYNC16(aB + off + (uint32_t)(r * 16 + c * 4) * 4,
                          Apk + (size_t)(rowBase + r) * WPR + kb + c * 4);
                CPASYNC16(bB + off + (uint32_t)(r * 16 + c * 4) * 4,
                          Bpk + (size_t)(cB + r) * WPR + kb + c * 4);
            }
            CPCOMMIT();
            CPWAIT(1);
        } else {
            CPWAIT(0);
        }
        __syncthreads();

        if ((G & 31) == 0) {
#pragma unroll
            for (int mt = 0; mt < 2; ++mt)
#pragma unroll
                for (int nt = 0; nt < 8; ++nt)
#pragma unroll
                    for (int c = 0; c < 4; ++c) acc[mt][nt][c] = 0.f;
        }

        {
            const uint32_t* A = Ab[G & 1];
            const uint32_t* B = Bb[G & 1];
            uint32_t ah[2][4], am[2][4];
#pragma unroll
            for (int mt = 0; mt < 2; ++mt) {
                const int r = wm * 32 + mt * 16 + gid;
                uint4 v = *(const uint4*)(A + r * 16 + tig * 4);
                uint4 w = *(const uint4*)(A + (r + 8) * 16 + tig * 4);
                ah[mt][0] = v.x; am[mt][0] = v.y; ah[mt][2] = v.z; am[mt][2] = v.w;
                ah[mt][1] = w.x; am[mt][1] = w.y; ah[mt][3] = w.z; am[mt][3] = w.w;
            }
#pragma unroll
            for (int nt = 0; nt < 8; ++nt) {
                const int cr = wn * 64 + nt * 8 + gid;
                uint4 b = *(const uint4*)(B + cr * 16 + tig * 4);
#pragma unroll
                for (int mt = 0; mt < 2; ++mt) {
                    MMA_BF16(acc[mt][nt], ah[mt], b.x, b.z);   // h*h
                    MMA_BF16(acc[mt][nt], ah[mt], b.y, b.w);   // h*m
                    MMA_BF16(acc[mt][nt], am[mt], b.x, b.z);   // m*h
                }
            }
        }
        __syncthreads();

        if ((G & 31) == 31) {
            const int ct = G >> 5;
#pragma unroll
            for (int mt = 0; mt < 2; ++mt)
#pragma unroll
                for (int nt = 0; nt < 8; ++nt)
#pragma unroll
                    for (int c = 0; c < 4; ++c) {
                        const int col = ct * 128 + wn * 64 + nt * 8 + tig * 2 + (c & 1);
                        const int s   = mt * 2 + (c >> 1);
                        float e2 = __ldg(&en2[col]);
                        float t  = __fadd_rn(myx2[s], e2);
                        float dd = __fmaf_rn(-2.0f, acc[mt][nt][c], t);
                        if (betterf(dd, col, b1d[s], b1i[s])) {
                            b2d[s] = b1d[s]; b2i[s] = b1i[s];
                            b1d[s] = dd;     b1i[s] = col;
                        } else if (betterf(dd, col, b2d[s], b2i[s])) {
                            b2d[s] = dd;     b2i[s] = col;
                        }
                    }
        }
    }

    // ---- top2 reduction: across tig (shfl), then across warp_n (smem) ----
#pragma unroll
    for (int s = 0; s < 4; ++s) {
        float d1 = b1d[s], d2 = b2d[s];
        int   i1 = b1i[s], i2 = b2i[s];
#pragma unroll
        for (int off = 1; off < 4; off <<= 1) {
            float pd1 = __shfl_xor_sync(0xFFFFFFFFu, d1, off);
            int   pi1 = __shfl_xor_sync(0xFFFFFFFFu, i1, off);
            float pd2 = __shfl_xor_sync(0xFFFFFFFFu, d2, off);
            int   pi2 = __shfl_xor_sync(0xFFFFFFFFu, i2, off);
            if (betterf(pd1, pi1, d1, i1)) {
                if (betterf(d1, i1, pd2, pi2)) { d2 = d1; i2 = i1; }
                else                           { d2 = pd2; i2 = pi2; }
                d1 = pd1; i1 = pi1;
            } else if (betterf(pd1, pi1, d2, i2)) {
                d2 = pd1; i2 = pi1;
            }
        }
        if (tig == 0) {
            const int row = wm * 32 + (s >> 1) * 16 + (s & 1) * 8 + gid;
            sd1[wn * 128 + row] = d1;  si1[wn * 128 + row] = i1;
            sd2[wn * 128 + row] = d2;  si2[wn * 128 + row] = i2;
        }
    }
    __syncthreads();

    if (tid < 128) {
        float d1 = sd1[tid], d2 = sd2[tid];
        int   i1 = si1[tid], i2 = si2[tid];
        {
            float pd1 = sd1[128 + tid], pd2 = sd2[128 + tid];
            int   pi1 = si1[128 + tid], pi2 = si2[128 + tid];
            if (betterf(pd1, pi1, d1, i1)) {
                if (betterf(d1, i1, pd2, pi2)) { d2 = d1; i2 = i1; }
                else                           { d2 = pd2; i2 = pi2; }
                d1 = pd1; i1 = pi1;
            } else if (betterf(pd1, pi1, d2, i2)) {
                d2 = pd1; i2 = pi1;
            }
        }
        int winner = i1;
        if (d2 - d1 <= MARGIN) {
            // exact fp32 rescore of the near-tied pair, reference semantics
            int ia = min(i1, i2), ib = max(i1, i2);
            const float* xr = Xex + (size_t)(rowBase + tid) * D;
            float x2v = __ldg(&rn2[rowBase + tid]);
            const float* ea = Eex + (size_t)ia * D;
            const float* eb = Eex + (size_t)ib * D;
            float xea = 0.f, xeb = 0.f;
            for (int k = 0; k < D; ++k) {
                float xv = __ldg(&xr[k]);
                xea = __fmaf_rn(xv, __ldg(&ea[k]), xea);
                xeb = __fmaf_rn(xv, __ldg(&eb[k]), xeb);
            }
            float da = __fmaf_rn(-2.f, xea, __fadd_rn(x2v, __ldg(&en2[ia])));
            float db = __fmaf_rn(-2.f, xeb, __fadd_rn(x2v, __ldg(&en2[ib])));
            winner = (db < da) ? ib : ia;   // tie -> lower index ia
        }
        outIdx[rowBase + tid] = winner;
    }
}

// ---------------------------------------------------------------------------
// Residual: R = X - E[idx] (exact fp32, matches reference) + ||R||^2.
// ---------------------------------------------------------------------------
__global__ void resid_kernel(const float* __restrict__ X, const float* __restrict__ E,
                             const int* __restrict__ idx, float* __restrict__ R,
                             float* __restrict__ r2)
{
    int row = blockIdx.x;
    int t   = threadIdx.x;     // 0..127
    int c   = idx[row];
    float4 xv = ((const float4*)(X + (size_t)row * D))[t];
    float4 ev = ((const float4*)(E + (size_t)c   * D))[t];
    float4 rv = make_float4(xv.x - ev.x, xv.y - ev.y, xv.z - ev.z, xv.w - ev.w);
    ((float4*)(R + (size_t)row * D))[t] = rv;

    float s = rv.x * rv.x + rv.y * rv.y + rv.z * rv.z + rv.w * rv.w;
#pragma unroll
    for (int o = 16; o; o >>= 1) s += __shfl_down_sync(0xFFFFFFFFu, s, o);
    __shared__ float red[4];
    if ((t & 31) == 0) red[t >> 5] = s;
    __syncthreads();
    if (t == 0) r2[row] = red[0] + red[1] + red[2] + red[3];
}

// ---------------------------------------------------------------------------
// Output: out = fl(x + fl(fl(e0+e1) - x))  (reference STE rounding)
// ---------------------------------------------------------------------------
__global__ void out_kernel(const float* __restrict__ X, const float* __restrict__ E0,
                           const float* __restrict__ E1, const int* __restrict__ i0,
                           const int* __restrict__ i1, float* __restrict__ out)
{
    int row = blockIdx.x;
    int t   = threadIdx.x;     // 0..127
    int c0  = i0[row];
    int c1  = i1[row];
    float4 xv = ((const float4*)(X  + (size_t)row * D))[t];
    float4 a  = ((const float4*)(E0 + (size_t)c0  * D))[t];
    float4 b  = ((const float4*)(E1 + (size_t)c1  * D))[t];
    float4 o;
    o.x = __fadd_rn(xv.x, __fadd_rn(__fadd_rn(a.x, b.x), -xv.x));
    o.y = __fadd_rn(xv.y, __fadd_rn(__fadd_rn(a.y, b.y), -xv.y));
    o.z = __fadd_rn(xv.z, __fadd_rn(__fadd_rn(a.z, b.z), -xv.z));
    o.w = __fadd_rn(xv.w, __fadd_rn(__fadd_rn(a.w, b.w), -xv.w));
    ((float4*)(out + (size_t)row * D))[t] = o;
}

// ---------------------------------------------------------------------------
extern "C" void kernel_launch(void* const* d_in, const int* in_sizes, int n_in,
                              void* d_out, int out_size)
{
    const float* x  = (const float*)d_in[0];
    const float* e0 = (const float*)d_in[1];
    const float* e1 = (const float*)d_in[2];
    float* out = (float*)d_out;

    int rows = in_sizes[0] / D;   // 32768
    int nc   = in_sizes[1] / D;   // 1024

    uint32_t *papk, *pe0pk, *pe1pk;
    float *pres, *px2, *pr2, *pe2a, *pe2b;
    int   *pi0, *pi1;
    cudaGetSymbolAddress((void**)&papk,  g_apk);
    cudaGetSymbolAddress((void**)&pe0pk, g_e0pk);
    cudaGetSymbolAddress((void**)&pe1pk, g_e1pk);
    cudaGetSymbolAddress((void**)&pres,  g_res);
    cudaGetSymbolAddress((void**)&px2,   g_x2);
    cudaGetSymbolAddress((void**)&pr2,   g_r2);
    cudaGetSymbolAddress((void**)&pe2a,  g_e2a);
    cudaGetSymbolAddress((void**)&pe2b,  g_e2b);
    cudaGetSymbolAddress((void**)&pi0,   g_idx0);
    cudaGetSymbolAddress((void**)&pi1,   g_idx1);

    pack_kernel<<<(rows * 32 + 255) / 256, 256>>>(x,  papk,  rows);
    pack_kernel<<<(nc   * 32 + 255) / 256, 256>>>(e0, pe0pk, nc);
    pack_kernel<<<(nc   * 32 + 255) / 256, 256>>>(e1, pe1pk, nc);

    rownorm_kernel<<<(rows + 7) / 8, 256>>>(x,  px2,  rows);
    rownorm_kernel<<<(nc   + 7) / 8, 256>>>(e0, pe2a, nc);
    rownorm_kernel<<<(nc   + 7) / 8, 256>>>(e1, pe2b, nc);

    stage_mma_kernel<<<rows / BM, 256>>>(papk, pe0pk, x, e0, px2, pe2a, pi0, nc);
    resid_kernel<<<rows, 128>>>(x, e0, pi0, pres, pr2);
    pack_kernel<<<(rows * 32 + 255) / 256, 256>>>(pres, papk, rows);
    stage_mma_kernel<<<rows / BM, 256>>>(papk, pe1pk, pres, e1, pr2, pe2b, pi1, nc);
    out_kernel<<<rows, 128>>>(x, e0, e1, pi0, pi1, out);
}

// round 10
// speedup vs baseline: 2.1885x; 1.0875x over previous
#include <cuda_runtime.h>
#include <cuda_bf16.h>
#include <math_constants.h>
#include <cstdint>

// ---------------------------------------------------------------------------
// RVQBottleneck: 2-stage residual VQ via mma.sync bf16 m16n8k16 3-term split.
//   dist = fl( fl(x2 + e2) - 2*xe ), argmin first-index tie break.
//   xe ~= h*h + h*m + m*h  (bf16 two-level split; dropped m*m ~ 2^-18)
// Near-ties (top2 within MARGIN) are exactly rescored in fp32.
// Packed layout per row / 16-k block (16 words): word[4t+0]=hi(2t,2t+1),
// [4t+1]=mid(2t,2t+1), [4t+2]=hi(2t+8,2t+9), [4t+3]=mid(2t+8,2t+9)
// -> one uint4 shared load = full hi+mid MMA fragments.
// Smem: 3x(8KB+8KB) stream buffers = 48KB static (the 0xc000 limit);
// top-2 reduction arrays alias Ab[0] after the mainloop (barrier-separated).
// ---------------------------------------------------------------------------

#define D        512
#define MAXROWS  32768
#define NCMAX    1024

#define BM   128
#define WPR  512
#define MARGIN 2.5e-4f

// ---- scratch (allocation-free) --------------------------------------------
__device__ uint32_t g_apk[(size_t)MAXROWS * WPR];
__device__ uint32_t g_e0pk[(size_t)NCMAX * WPR];
__device__ uint32_t g_e1pk[(size_t)NCMAX * WPR];
__device__ float    g_res[(size_t)MAXROWS * D];
__device__ float    g_x2[MAXROWS];
__device__ float    g_r2[MAXROWS];
__device__ float    g_e2a[NCMAX];
__device__ float    g_e2b[NCMAX];
__device__ int      g_idx0[MAXROWS];
__device__ int      g_idx1[MAXROWS];

// ---- helpers --------------------------------------------------------------
__device__ __forceinline__ uint32_t bf16pack(float lo, float hi_) {
    uint32_t r;
    asm("cvt.rn.bf16x2.f32 %0, %1, %2;" : "=r"(r) : "f"(hi_), "f"(lo));
    return r;
}
__device__ __forceinline__ float bf16round(float x) {
    return __bfloat162float(__float2bfloat16(x));
}
#define CPASYNC16(dst, src) \
    asm volatile("cp.async.cg.shared.global [%0], [%1], 16;" :: "r"(dst), "l"(src) : "memory")
#define CPCOMMIT() asm volatile("cp.async.commit_group;" ::: "memory")
#define CPWAIT(n)  asm volatile("cp.async.wait_group %0;" :: "n"(n) : "memory")

#define MMA_BF16(d, a, b0, b1) \
    asm volatile("mma.sync.aligned.m16n8k16.row.col.f32.bf16.bf16.f32 " \
        "{%0,%1,%2,%3}, {%4,%5,%6,%7}, {%8,%9}, {%0,%1,%2,%3};" \
        : "+f"((d)[0]), "+f"((d)[1]), "+f"((d)[2]), "+f"((d)[3]) \
        : "r"((a)[0]), "r"((a)[1]), "r"((a)[2]), "r"((a)[3]), "r"(b0), "r"(b1))

__device__ __forceinline__ bool betterf(float d, int i, float rd, int ri) {
    return d < rd || (d == rd && i < ri);
}
__device__ __forceinline__ uint32_t smem_u32_of(const void* p) {
    uint32_t a;
    asm("{ .reg .u64 t; cvta.to.shared.u64 t, %1; cvt.u32.u64 %0, t; }"
        : "=r"(a) : "l"(p));
    return a;
}

// ---------------------------------------------------------------------------
// Pack fp32 -> interleaved bf16 hi/mid words. One thread per (row,16k-block).
// ---------------------------------------------------------------------------
__device__ __forceinline__ void pack16(const float* __restrict__ s, uint4* d)
{
    float f[16];
    float4 F0 = ((const float4*)s)[0], F1 = ((const float4*)s)[1];
    float4 F2 = ((const float4*)s)[2], F3 = ((const float4*)s)[3];
    f[0]=F0.x; f[1]=F0.y; f[2]=F0.z; f[3]=F0.w;
    f[4]=F1.x; f[5]=F1.y; f[6]=F1.z; f[7]=F1.w;
    f[8]=F2.x; f[9]=F2.y; f[10]=F2.z; f[11]=F2.w;
    f[12]=F3.x; f[13]=F3.y; f[14]=F3.z; f[15]=F3.w;
#pragma unroll
    for (int t = 0; t < 4; ++t) {
        float x0 = f[2*t],   x1 = f[2*t+1];
        float x2 = f[2*t+8], x3 = f[2*t+9];
        uint4 w;
        w.x = bf16pack(x0, x1);
        w.y = bf16pack(x0 - bf16round(x0), x1 - bf16round(x1));
        w.z = bf16pack(x2, x3);
        w.w = bf16pack(x2 - bf16round(x2), x3 - bf16round(x3));
        d[t] = w;
    }
}

__global__ void pack_kernel(const float* __restrict__ src,
                            uint32_t* __restrict__ dst, int nrows)
{
    int i = blockIdx.x * blockDim.x + threadIdx.x;
    if (i >= nrows * 32) return;
    int row = i >> 5, blk = i & 31;
    pack16(src + (size_t)row * D + blk * 16,
           (uint4*)(dst + (size_t)row * WPR + blk * 16));
}

// Both codebooks in one launch.
__global__ void pack2_kernel(const float* __restrict__ e0, const float* __restrict__ e1,
                             uint32_t* __restrict__ d0, uint32_t* __restrict__ d1, int nc)
{
    int i = blockIdx.x * blockDim.x + threadIdx.x;
    if (i >= nc * 64) return;
    const float* src = (i < nc * 32) ? e0 : e1;
    uint32_t*    dst = (i < nc * 32) ? d0 : d1;
    int j = (i < nc * 32) ? i : i - nc * 32;
    int row = j >> 5, blk = j & 31;
    pack16(src + (size_t)row * D + blk * 16,
           (uint4*)(dst + (size_t)row * WPR + blk * 16));
}

// ---------------------------------------------------------------------------
// All three row-norm sets in one launch (bit-exact summation order kept).
// ---------------------------------------------------------------------------
__global__ void norm3_kernel(const float* __restrict__ x,  float* __restrict__ dx,
                             const float* __restrict__ e0, float* __restrict__ d0,
                             const float* __restrict__ e1, float* __restrict__ d1,
                             int rows, int nc)
{
    int gr = blockIdx.x * 8 + (threadIdx.x >> 5);
    const float* src; float* dst; int row;
    if (gr < rows)            { src = x;  dst = dx; row = gr; }
    else if (gr < rows + nc)  { src = e0; dst = d0; row = gr - rows; }
    else if (gr < rows + 2*nc){ src = e1; dst = d1; row = gr - rows - nc; }
    else return;
    int lane = threadIdx.x & 31;
    const float4* p = (const float4*)(src + (size_t)row * D);
    float s = 0.f;
#pragma unroll
    for (int i = 0; i < D / 128; i++) {
        float4 v = p[lane + 32 * i];
        s += v.x * v.x + v.y * v.y + v.z * v.z + v.w * v.w;
    }
#pragma unroll
    for (int o = 16; o; o >>= 1) s += __shfl_down_sync(0xFFFFFFFFu, s, o);
    if (lane == 0) dst[row] = s;
}

// ---------------------------------------------------------------------------
// Fused bf16-MMA GEMM + argmin stage. 256 thr, warp tile 32x64, BM=128.
// Triple-buffered chunks (16 k each) -> single __syncthreads per chunk.
// ---------------------------------------------------------------------------
__global__ __launch_bounds__(256, 2)
void stage_mma_kernel(const uint32_t* __restrict__ Apk,
                      const uint32_t* __restrict__ Bpk,
                      const float* __restrict__ Xex, const float* __restrict__ Eex,
                      const float* __restrict__ rn2, const float* __restrict__ en2,
                      int* __restrict__ outIdx, int ncodes)
{
    __shared__ uint32_t Ab[3][2048];   // 8KB per buffer
    __shared__ uint32_t Bb[3][2048];   // total static smem = 48KB exactly

    const uint32_t aB = smem_u32_of(Ab);
    const uint32_t bB = smem_u32_of(Bb);

    const int tid  = threadIdx.x;
    const int lane = tid & 31;
    const int wid  = tid >> 5;
    const int wm   = wid & 3;
    const int wn   = wid >> 2;
    const int gid  = lane >> 2;
    const int tig  = lane & 3;
    const int rowBase = blockIdx.x * BM;

    float myx2[4];
#pragma unroll
    for (int s = 0; s < 4; ++s)
        myx2[s] = __ldg(&rn2[rowBase + wm * 32 + (s >> 1) * 16 + (s & 1) * 8 + gid]);

    float b1d[4], b2d[4];
    int   b1i[4], b2i[4];
#pragma unroll
    for (int s = 0; s < 4; ++s) {
        b1d[s] = CUDART_INF_F; b1i[s] = 0x7FFFFFFF;
        b2d[s] = CUDART_INF_F; b2i[s] = 0x7FFFFFFF;
    }

    float acc[2][8][4];

    const int NCT = ncodes >> 7;
    const int NG  = NCT * 32;

    // thread's cp.async slots: 2 per matrix per chunk
    const int r0 = tid >> 2, c0 = tid & 3;             // j = tid
    const int r1 = (tid + 256) >> 2, c1 = tid & 3;     // j = tid+256

    for (int G = 0; G < NG; ++G) {
        if (G == 0) {
            CPASYNC16(aB + (uint32_t)(r0 * 16 + c0 * 4) * 4,
                      Apk + (size_t)(rowBase + r0) * WPR + c0 * 4);
            CPASYNC16(bB + (uint32_t)(r0 * 16 + c0 * 4) * 4,
                      Bpk + (size_t)r0 * WPR + c0 * 4);
            CPASYNC16(aB + (uint32_t)(r1 * 16 + c1 * 4) * 4,
                      Apk + (size_t)(rowBase + r1) * WPR + c1 * 4);
            CPASYNC16(bB + (uint32_t)(r1 * 16 + c1 * 4) * 4,
                      Bpk + (size_t)r1 * WPR + c1 * 4);
            CPCOMMIT();
        }
        if (G + 1 < NG) {
            const int g1 = G + 1;
            const int kb = (g1 & 31) * 16, cB = (g1 >> 5) << 7;
            const uint32_t off = (uint32_t)(g1 % 3) * 8192u;
            CPASYNC16(aB + off + (uint32_t)(r0 * 16 + c0 * 4) * 4,
                      Apk + (size_t)(rowBase + r0) * WPR + kb + c0 * 4);
            CPASYNC16(bB + off + (uint32_t)(r0 * 16 + c0 * 4) * 4,
                      Bpk + (size_t)(cB + r0) * WPR + kb + c0 * 4);
            CPASYNC16(aB + off + (uint32_t)(r1 * 16 + c1 * 4) * 4,
                      Apk + (size_t)(rowBase + r1) * WPR + kb + c1 * 4);
            CPASYNC16(bB + off + (uint32_t)(r1 * 16 + c1 * 4) * 4,
                      Bpk + (size_t)(cB + r1) * WPR + kb + c1 * 4);
            CPCOMMIT();
            CPWAIT(1);
        } else {
            CPWAIT(0);
        }
        __syncthreads();   // single barrier per chunk (triple buffer)

        if ((G & 31) == 0) {
#pragma unroll
            for (int mt = 0; mt < 2; ++mt)
#pragma unroll
                for (int nt = 0; nt < 8; ++nt)
#pragma unroll
                    for (int c = 0; c < 4; ++c) acc[mt][nt][c] = 0.f;
        }

        {
            const uint32_t* A = Ab[G % 3];
            const uint32_t* B = Bb[G % 3];
            uint32_t ah[2][4], am[2][4];
#pragma unroll
            for (int mt = 0; mt < 2; ++mt) {
                const int r = wm * 32 + mt * 16 + gid;
                uint4 v = *(const uint4*)(A + r * 16 + tig * 4);
                uint4 w = *(const uint4*)(A + (r + 8) * 16 + tig * 4);
                ah[mt][0] = v.x; am[mt][0] = v.y; ah[mt][2] = v.z; am[mt][2] = v.w;
                ah[mt][1] = w.x; am[mt][1] = w.y; ah[mt][3] = w.z; am[mt][3] = w.w;
            }
#pragma unroll
            for (int nt = 0; nt < 8; ++nt) {
                const int cr = wn * 64 + nt * 8 + gid;
                uint4 b = *(const uint4*)(B + cr * 16 + tig * 4);
#pragma unroll
                for (int mt = 0; mt < 2; ++mt) {
                    MMA_BF16(acc[mt][nt], ah[mt], b.x, b.z);   // h*h
                    MMA_BF16(acc[mt][nt], ah[mt], b.y, b.w);   // h*m
                    MMA_BF16(acc[mt][nt], am[mt], b.x, b.z);   // m*h
                }
            }
        }

        if ((G & 31) == 31) {
            const int ct = G >> 5;
#pragma unroll
            for (int mt = 0; mt < 2; ++mt)
#pragma unroll
                for (int nt = 0; nt < 8; ++nt)
#pragma unroll
                    for (int c = 0; c < 4; ++c) {
                        const int col = ct * 128 + wn * 64 + nt * 8 + tig * 2 + (c & 1);
                        const int s   = mt * 2 + (c >> 1);
                        float e2 = __ldg(&en2[col]);
                        float t  = __fadd_rn(myx2[s], e2);
                        float dd = __fmaf_rn(-2.0f, acc[mt][nt][c], t);
                        if (betterf(dd, col, b1d[s], b1i[s])) {
                            b2d[s] = b1d[s]; b2i[s] = b1i[s];
                            b1d[s] = dd;     b1i[s] = col;
                        } else if (betterf(dd, col, b2d[s], b2i[s])) {
                            b2d[s] = dd;     b2i[s] = col;
                        }
                    }
        }
    }

    // stream buffers are dead now; alias the top-2 reduction arrays onto Ab[0]
    __syncthreads();
    float* sd1 = (float*)&Ab[0][0];
    int*   si1 = (int*)  &Ab[0][256];
    float* sd2 = (float*)&Ab[0][512];
    int*   si2 = (int*)  &Ab[0][768];

    // ---- top2 reduction: across tig (shfl), then across warp_n (smem) ----
#pragma unroll
    for (int s = 0; s < 4; ++s) {
        float d1 = b1d[s], d2 = b2d[s];
        int   i1 = b1i[s], i2 = b2i[s];
#pragma unroll
        for (int off = 1; off < 4; off <<= 1) {
            float pd1 = __shfl_xor_sync(0xFFFFFFFFu, d1, off);
            int   pi1 = __shfl_xor_sync(0xFFFFFFFFu, i1, off);
            float pd2 = __shfl_xor_sync(0xFFFFFFFFu, d2, off);
            int   pi2 = __shfl_xor_sync(0xFFFFFFFFu, i2, off);
            if (betterf(pd1, pi1, d1, i1)) {
                if (betterf(d1, i1, pd2, pi2)) { d2 = d1; i2 = i1; }
                else                           { d2 = pd2; i2 = pi2; }
                d1 = pd1; i1 = pi1;
            } else if (betterf(pd1, pi1, d2, i2)) {
                d2 = pd1; i2 = pi1;
            }
        }
        if (tig == 0) {
            const int row = wm * 32 + (s >> 1) * 16 + (s & 1) * 8 + gid;
            sd1[wn * 128 + row] = d1;  si1[wn * 128 + row] = i1;
            sd2[wn * 128 + row] = d2;  si2[wn * 128 + row] = i2;
        }
    }
    __syncthreads();

    if (tid < 128) {
        float d1 = sd1[tid], d2 = sd2[tid];
        int   i1 = si1[tid], i2 = si2[tid];
        {
            float pd1 = sd1[128 + tid], pd2 = sd2[128 + tid];
            int   pi1 = si1[128 + tid], pi2 = si2[128 + tid];
            if (betterf(pd1, pi1, d1, i1)) {
                if (betterf(d1, i1, pd2, pi2)) { d2 = d1; i2 = i1; }
                else                           { d2 = pd2; i2 = pi2; }
                d1 = pd1; i1 = pi1;
            } else if (betterf(pd1, pi1, d2, i2)) {
                d2 = pd1; i2 = pi1;
            }
        }
        int winner = i1;
        if (d2 - d1 <= MARGIN) {
            int ia = min(i1, i2), ib = max(i1, i2);
            const float* xr = Xex + (size_t)(rowBase + tid) * D;
            float x2v = __ldg(&rn2[rowBase + tid]);
            const float* ea = Eex + (size_t)ia * D;
            const float* eb = Eex + (size_t)ib * D;
            float xea = 0.f, xeb = 0.f;
            for (int k = 0; k < D; ++k) {
                float xv = __ldg(&xr[k]);
                xea = __fmaf_rn(xv, __ldg(&ea[k]), xea);
                xeb = __fmaf_rn(xv, __ldg(&eb[k]), xeb);
            }
            float da = __fmaf_rn(-2.f, xea, __fadd_rn(x2v, __ldg(&en2[ia])));
            float db = __fmaf_rn(-2.f, xeb, __fadd_rn(x2v, __ldg(&en2[ib])));
            winner = (db < da) ? ib : ia;
        }
        outIdx[rowBase + tid] = winner;
    }
}

// ---------------------------------------------------------------------------
// Fused: R = X - E[idx] (exact fp32) + write R + write packed R + ||R||^2.
// One 128-thread block per row; thread t owns k in [4t, 4t+4).
// ---------------------------------------------------------------------------
__global__ void residpack_kernel(const float* __restrict__ X, const float* __restrict__ E,
                                 const int* __restrict__ idx,
                                 float* __restrict__ R, uint32_t* __restrict__ Rpk,
                                 float* __restrict__ r2)
{
    int row = blockIdx.x;
    int t   = threadIdx.x;     // 0..127
    int c   = idx[row];
    float4 xv = ((const float4*)(X + (size_t)row * D))[t];
    float4 ev = ((const float4*)(E + (size_t)c   * D))[t];
    float4 rv = make_float4(xv.x - ev.x, xv.y - ev.y, xv.z - ev.z, xv.w - ev.w);
    ((float4*)(R + (size_t)row * D))[t] = rv;

    // pack 2 pairs: (4t,4t+1) and (4t+2,4t+3) into interleaved hi/mid words
    {
        uint32_t* dst = Rpk + (size_t)row * WPR;
        int blk = t >> 2;              // 16-k block = t/4
        int a   = t & 3;               // position within block: j = 4a..4a+3
        uint32_t whi0 = bf16pack(rv.x, rv.y);
        uint32_t wmi0 = bf16pack(rv.x - bf16round(rv.x), rv.y - bf16round(rv.y));
        uint32_t whi1 = bf16pack(rv.z, rv.w);
        uint32_t wmi1 = bf16pack(rv.z - bf16round(rv.z), rv.w - bf16round(rv.w));
        int w0 = (a < 2) ? 8 * a     : 8 * (a - 2) + 2;
        int w1 = (a < 2) ? 8 * a + 4 : 8 * (a - 2) + 6;
        dst[blk * 16 + w0]     = whi0;
        dst[blk * 16 + w0 + 1] = wmi0;
        dst[blk * 16 + w1]     = whi1;
        dst[blk * 16 + w1 + 1] = wmi1;
    }

    float s = rv.x * rv.x + rv.y * rv.y + rv.z * rv.z + rv.w * rv.w;
#pragma unroll
    for (int o = 16; o; o >>= 1) s += __shfl_down_sync(0xFFFFFFFFu, s, o);
    __shared__ float red[4];
    if ((t & 31) == 0) red[t >> 5] = s;
    __syncthreads();
    if (t == 0) r2[row] = red[0] + red[1] + red[2] + red[3];
}

// ---------------------------------------------------------------------------
// Output: out = fl(x + fl(fl(e0+e1) - x))  (reference STE rounding)
// ---------------------------------------------------------------------------
__global__ void out_kernel(const float* __restrict__ X, const float* __restrict__ E0,
                           const float* __restrict__ E1, const int* __restrict__ i0,
                           const int* __restrict__ i1, float* __restrict__ out)
{
    int row = blockIdx.x;
    int t   = threadIdx.x;
    int c0  = i0[row];
    int c1  = i1[row];
    float4 xv = ((const float4*)(X  + (size_t)row * D))[t];
    float4 a  = ((const float4*)(E0 + (size_t)c0  * D))[t];
    float4 b  = ((const float4*)(E1 + (size_t)c1  * D))[t];
    float4 o;
    o.x = __fadd_rn(xv.x, __fadd_rn(__fadd_rn(a.x, b.x), -xv.x));
    o.y = __fadd_rn(xv.y, __fadd_rn(__fadd_rn(a.y, b.y), -xv.y));
    o.z = __fadd_rn(xv.z, __fadd_rn(__fadd_rn(a.z, b.z), -xv.z));
    o.w = __fadd_rn(xv.w, __fadd_rn(__fadd_rn(a.w, b.w), -xv.w));
    ((float4*)(out + (size_t)row * D))[t] = o;
}

// ---------------------------------------------------------------------------
extern "C" void kernel_launch(void* const* d_in, const int* in_sizes, int n_in,
                              void* d_out, int out_size)
{
    const float* x  = (const float*)d_in[0];
    const float* e0 = (const float*)d_in[1];
    const float* e1 = (const float*)d_in[2];
    float* out = (float*)d_out;

    int rows = in_sizes[0] / D;   // 32768
    int nc   = in_sizes[1] / D;   // 1024

    uint32_t *papk, *pe0pk, *pe1pk;
    float *pres, *px2, *pr2, *pe2a, *pe2b;
    int   *pi0, *pi1;
    cudaGetSymbolAddress((void**)&papk,  g_apk);
    cudaGetSymbolAddress((void**)&pe0pk, g_e0pk);
    cudaGetSymbolAddress((void**)&pe1pk, g_e1pk);
    cudaGetSymbolAddress((void**)&pres,  g_res);
    cudaGetSymbolAddress((void**)&px2,   g_x2);
    cudaGetSymbolAddress((void**)&pr2,   g_r2);
    cudaGetSymbolAddress((void**)&pe2a,  g_e2a);
    cudaGetSymbolAddress((void**)&pe2b,  g_e2b);
    cudaGetSymbolAddress((void**)&pi0,   g_idx0);
    cudaGetSymbolAddress((void**)&pi1,   g_idx1);

    // launch order keeps stage_mma_kernel at capture index 3
    pack_kernel<<<(rows * 32 + 255) / 256, 256>>>(x, papk, rows);
    pack2_kernel<<<(nc * 64 + 255) / 256, 256>>>(e0, e1, pe0pk, pe1pk, nc);
    norm3_kernel<<<(rows + 2 * nc + 7) / 8, 256>>>(x, px2, e0, pe2a, e1, pe2b,
                                                   rows, nc);
    stage_mma_kernel<<<rows / BM, 256>>>(papk, pe0pk, x, e0, px2, pe2a, pi0, nc);
    residpack_kernel<<<rows, 128>>>(x, e0, pi0, pres, papk, pr2);
    stage_mma_kernel<<<rows / BM, 256>>>(papk, pe1pk, pres, e1, pr2, pe2b, pi1, nc);
    out_kernel<<<rows, 128>>>(x, e0, e1, pi0, pi1, out);
}

// round 11
// speedup vs baseline: 2.2530x; 1.0295x over previous
#include <cuda_runtime.h>
#include <cuda_bf16.h>
#include <math_constants.h>
#include <cstdint>

// ---------------------------------------------------------------------------
// RVQBottleneck: 2-stage residual VQ via mma.sync bf16 m16n8k16 3-term split.
//   dist = fl( fl(x2 + e2) - 2*xe ), argmin first-index tie break.
//   xe ~= h*h + h*m + m*h  (bf16 two-level split; dropped m*m ~ 2^-18)
// Near-ties (top2 within MARGIN) are exactly rescored in fp32.
// Packed layout per row / 16-k block (16 words): word[4t+0]=hi(2t,2t+1),
// [4t+1]=mid(2t,2t+1), [4t+2]=hi(2t+8,2t+9), [4t+3]=mid(2t+8,2t+9).
// Stage kernel: 32-k chunks, triple-buffered in 96KB DYNAMIC smem, one
// barrier per chunk, XOR-swizzled rows for conflict-free LDS.128.
// ---------------------------------------------------------------------------

#define D        512
#define MAXROWS  32768
#define NCMAX    1024

#define BM   128
#define WPR  512
#define MARGIN 2.5e-4f

#define BUF_WORDS 8192u            // per stream buffer: A 4096 + B 4096 words
#define SMEM_DYN  (3 * BUF_WORDS * 4)   // 98304 bytes

// ---- scratch (allocation-free) --------------------------------------------
__device__ uint32_t g_apk[(size_t)MAXROWS * WPR];
__device__ uint32_t g_e0pk[(size_t)NCMAX * WPR];
__device__ uint32_t g_e1pk[(size_t)NCMAX * WPR];
__device__ float    g_res[(size_t)MAXROWS * D];
__device__ float    g_x2[MAXROWS];
__device__ float    g_r2[MAXROWS];
__device__ float    g_e2a[NCMAX];
__device__ float    g_e2b[NCMAX];
__device__ int      g_idx0[MAXROWS];
__device__ int      g_idx1[MAXROWS];

// ---- helpers --------------------------------------------------------------
__device__ __forceinline__ uint32_t bf16pack(float lo, float hi_) {
    uint32_t r;
    asm("cvt.rn.bf16x2.f32 %0, %1, %2;" : "=r"(r) : "f"(hi_), "f"(lo));
    return r;
}
__device__ __forceinline__ float bf16round(float x) {
    return __bfloat162float(__float2bfloat16(x));
}
#define CPASYNC16(dst, src) \
    asm volatile("cp.async.cg.shared.global [%0], [%1], 16;" :: "r"(dst), "l"(src) : "memory")
#define CPCOMMIT() asm volatile("cp.async.commit_group;" ::: "memory")
#define CPWAIT(n)  asm volatile("cp.async.wait_group %0;" :: "n"(n) : "memory")

#define MMA_BF16(d, a, b0, b1) \
    asm volatile("mma.sync.aligned.m16n8k16.row.col.f32.bf16.bf16.f32 " \
        "{%0,%1,%2,%3}, {%4,%5,%6,%7}, {%8,%9}, {%0,%1,%2,%3};" \
        : "+f"((d)[0]), "+f"((d)[1]), "+f"((d)[2]), "+f"((d)[3]) \
        : "r"((a)[0]), "r"((a)[1]), "r"((a)[2]), "r"((a)[3]), "r"(b0), "r"(b1))

__device__ __forceinline__ bool betterf(float d, int i, float rd, int ri) {
    return d < rd || (d == rd && i < ri);
}
__device__ __forceinline__ uint32_t smem_u32_of(const void* p) {
    uint32_t a;
    asm("{ .reg .u64 t; cvta.to.shared.u64 t, %1; cvt.u32.u64 %0, t; }"
        : "=r"(a) : "l"(p));
    return a;
}

// ---------------------------------------------------------------------------
// Pack fp32 -> interleaved bf16 hi/mid words. One thread per (row,16k-block).
// ---------------------------------------------------------------------------
__device__ __forceinline__ void pack16(const float* __restrict__ s, uint4* d)
{
    float f[16];
    float4 F0 = ((const float4*)s)[0], F1 = ((const float4*)s)[1];
    float4 F2 = ((const float4*)s)[2], F3 = ((const float4*)s)[3];
    f[0]=F0.x; f[1]=F0.y; f[2]=F0.z; f[3]=F0.w;
    f[4]=F1.x; f[5]=F1.y; f[6]=F1.z; f[7]=F1.w;
    f[8]=F2.x; f[9]=F2.y; f[10]=F2.z; f[11]=F2.w;
    f[12]=F3.x; f[13]=F3.y; f[14]=F3.z; f[15]=F3.w;
#pragma unroll
    for (int t = 0; t < 4; ++t) {
        float x0 = f[2*t],   x1 = f[2*t+1];
        float x2 = f[2*t+8], x3 = f[2*t+9];
        uint4 w;
        w.x = bf16pack(x0, x1);
        w.y = bf16pack(x0 - bf16round(x0), x1 - bf16round(x1));
        w.z = bf16pack(x2, x3);
        w.w = bf16pack(x2 - bf16round(x2), x3 - bf16round(x3));
        d[t] = w;
    }
}

__global__ void pack_kernel(const float* __restrict__ src,
                            uint32_t* __restrict__ dst, int nrows)
{
    int i = blockIdx.x * blockDim.x + threadIdx.x;
    if (i >= nrows * 32) return;
    int row = i >> 5, blk = i & 31;
    pack16(src + (size_t)row * D + blk * 16,
           (uint4*)(dst + (size_t)row * WPR + blk * 16));
}

// Both codebooks in one launch.
__global__ void pack2_kernel(const float* __restrict__ e0, const float* __restrict__ e1,
                             uint32_t* __restrict__ d0, uint32_t* __restrict__ d1, int nc)
{
    int i = blockIdx.x * blockDim.x + threadIdx.x;
    if (i >= nc * 64) return;
    const float* src = (i < nc * 32) ? e0 : e1;
    uint32_t*    dst = (i < nc * 32) ? d0 : d1;
    int j = (i < nc * 32) ? i : i - nc * 32;
    int row = j >> 5, blk = j & 31;
    pack16(src + (size_t)row * D + blk * 16,
           (uint4*)(dst + (size_t)row * WPR + blk * 16));
}

// ---------------------------------------------------------------------------
// All three row-norm sets in one launch (bit-exact summation order kept).
// ---------------------------------------------------------------------------
__global__ void norm3_kernel(const float* __restrict__ x,  float* __restrict__ dx,
                             const float* __restrict__ e0, float* __restrict__ d0,
                             const float* __restrict__ e1, float* __restrict__ d1,
                             int rows, int nc)
{
    int gr = blockIdx.x * 8 + (threadIdx.x >> 5);
    const float* src; float* dst; int row;
    if (gr < rows)            { src = x;  dst = dx; row = gr; }
    else if (gr < rows + nc)  { src = e0; dst = d0; row = gr - rows; }
    else if (gr < rows + 2*nc){ src = e1; dst = d1; row = gr - rows - nc; }
    else return;
    int lane = threadIdx.x & 31;
    const float4* p = (const float4*)(src + (size_t)row * D);
    float s = 0.f;
#pragma unroll
    for (int i = 0; i < D / 128; i++) {
        float4 v = p[lane + 32 * i];
        s += v.x * v.x + v.y * v.y + v.z * v.z + v.w * v.w;
    }
#pragma unroll
    for (int o = 16; o; o >>= 1) s += __shfl_down_sync(0xFFFFFFFFu, s, o);
    if (lane == 0) dst[row] = s;
}

// ---------------------------------------------------------------------------
// Fused bf16-MMA GEMM + argmin stage. 256 thr, warp tile 32x64, BM=128.
// 32-k chunks, triple buffered (dynamic smem), one barrier per chunk.
// Smem row = 32 words (128B); uint4 slot c swizzled by
// key(row) = ((row&1)<<2)|((row>>1)&3)  -> conflict-free LDS.128 phases.
// ---------------------------------------------------------------------------
__global__ __launch_bounds__(256, 2)
void stage_mma_kernel(const uint32_t* __restrict__ Apk,
                      const uint32_t* __restrict__ Bpk,
                      const float* __restrict__ Xex, const float* __restrict__ Eex,
                      const float* __restrict__ rn2, const float* __restrict__ en2,
                      int* __restrict__ outIdx, int ncodes)
{
    extern __shared__ uint32_t SM[];
    const uint32_t sA = smem_u32_of(SM);

    const int tid  = threadIdx.x;
    const int lane = tid & 31;
    const int wid  = tid >> 5;
    const int wm   = wid & 3;
    const int wn   = wid >> 2;
    const int gid  = lane >> 2;
    const int tig  = lane & 3;
    const int rowBase = blockIdx.x * BM;

    // per-thread cp.async geometry: u = tid + 256*m -> row = row0+32m, c = tid&7
    const int row0 = tid >> 3;
    const int c0   = tid & 7;
    const int keyS = ((row0 & 1) << 2) | ((row0 >> 1) & 3);
    const uint32_t aD0 = (uint32_t)(row0 * 32 + ((c0 ^ keyS) << 2));   // word off
    const uint32_t* As0 = Apk + (size_t)(rowBase + row0) * WPR + c0 * 4;
    const uint32_t* Bs0 = Bpk + (size_t)row0 * WPR + c0 * 4;

    const int keyg = ((gid & 1) << 2) | ((gid >> 1) & 3);

    float myx2[4];
#pragma unroll
    for (int s = 0; s < 4; ++s)
        myx2[s] = __ldg(&rn2[rowBase + wm * 32 + (s >> 1) * 16 + (s & 1) * 8 + gid]);

    float b1d[4], b2d[4];
    int   b1i[4], b2i[4];
#pragma unroll
    for (int s = 0; s < 4; ++s) {
        b1d[s] = CUDART_INF_F; b1i[s] = 0x7FFFFFFF;
        b2d[s] = CUDART_INF_F; b2i[s] = 0x7FFFFFFF;
    }

    float acc[2][8][4];

    const int NCT = ncodes >> 7;
    const int NIT = NCT * 16;          // 32-k chunks

    // prefetch chunk 0 into buffer 0
#pragma unroll
    for (int m = 0; m < 4; ++m) {
        CPASYNC16(sA + (aD0 + 1024u * m) * 4,          As0 + 16384u * m);
        CPASYNC16(sA + (4096u + aD0 + 1024u * m) * 4,  Bs0 + 16384u * m);
    }
    CPCOMMIT();

    int bufc = 0, bufp = 1;
    for (int it = 0; it < NIT; ++it) {
        if (it + 1 < NIT) {
            const int g1 = it + 1;
            const uint32_t boff = (uint32_t)bufp * BUF_WORDS;
            const uint32_t kb1  = (uint32_t)(g1 & 15) * 32u;
            const uint32_t cb1  = (uint32_t)(g1 >> 4) * 65536u;
#pragma unroll
            for (int m = 0; m < 4; ++m) {
                CPASYNC16(sA + (boff + aD0 + 1024u * m) * 4,
                          As0 + 16384u * m + kb1);
                CPASYNC16(sA + (boff + 4096u + aD0 + 1024u * m) * 4,
                          Bs0 + 16384u * m + cb1 + kb1);
            }
            CPCOMMIT();
            CPWAIT(1);
        } else {
            CPWAIT(0);
        }
        __syncthreads();   // single barrier per chunk (triple buffer)

        if ((it & 15) == 0) {
#pragma unroll
            for (int mt = 0; mt < 2; ++mt)
#pragma unroll
                for (int nt = 0; nt < 8; ++nt)
#pragma unroll
                    for (int c = 0; c < 4; ++c) acc[mt][nt][c] = 0.f;
        }

        {
            const uint32_t* A = SM + (uint32_t)bufc * BUF_WORDS;
            const uint32_t* B = A + 4096;
#pragma unroll
            for (int h = 0; h < 2; ++h) {
                const int j4s = ((h << 2) | tig) ^ keyg;
                uint32_t ah[2][4], am[2][4];
#pragma unroll
                for (int mt = 0; mt < 2; ++mt) {
                    const int r = wm * 32 + mt * 16 + gid;
                    uint4 v = *(const uint4*)(A + r * 32 + j4s * 4);
                    uint4 w = *(const uint4*)(A + (r + 8) * 32 + j4s * 4);
                    ah[mt][0] = v.x; am[mt][0] = v.y; ah[mt][2] = v.z; am[mt][2] = v.w;
                    ah[mt][1] = w.x; am[mt][1] = w.y; ah[mt][3] = w.z; am[mt][3] = w.w;
                }
#pragma unroll
                for (int nt = 0; nt < 8; ++nt) {
                    const int cr = wn * 64 + nt * 8 + gid;
                    uint4 b = *(const uint4*)(B + cr * 32 + j4s * 4);
#pragma unroll
                    for (int mt = 0; mt < 2; ++mt) {
                        MMA_BF16(acc[mt][nt], ah[mt], b.x, b.z);   // h*h
                        MMA_BF16(acc[mt][nt], ah[mt], b.y, b.w);   // h*m
                        MMA_BF16(acc[mt][nt], am[mt], b.x, b.z);   // m*h
                    }
                }
            }
        }

        if ((it & 15) == 15) {
            const int ct = it >> 4;
#pragma unroll
            for (int mt = 0; mt < 2; ++mt)
#pragma unroll
                for (int nt = 0; nt < 8; ++nt)
#pragma unroll
                    for (int c = 0; c < 4; ++c) {
                        const int col = ct * 128 + wn * 64 + nt * 8 + tig * 2 + (c & 1);
                        const int s   = mt * 2 + (c >> 1);
                        float e2 = __ldg(&en2[col]);
                        float t  = __fadd_rn(myx2[s], e2);
                        float dd = __fmaf_rn(-2.0f, acc[mt][nt][c], t);
                        if (betterf(dd, col, b1d[s], b1i[s])) {
                            b2d[s] = b1d[s]; b2i[s] = b1i[s];
                            b1d[s] = dd;     b1i[s] = col;
                        } else if (betterf(dd, col, b2d[s], b2i[s])) {
                            b2d[s] = dd;     b2i[s] = col;
                        }
                    }
        }

        bufc = (bufc == 2) ? 0 : bufc + 1;
        bufp = (bufp == 2) ? 0 : bufp + 1;
    }

    // stream buffers dead; alias top-2 reduction arrays onto SM (barrier first)
    __syncthreads();
    float* sd1 = (float*)&SM[0];
    int*   si1 = (int*)  &SM[256];
    float* sd2 = (float*)&SM[512];
    int*   si2 = (int*)  &SM[768];

    // ---- top2 reduction: across tig (shfl), then across warp_n (smem) ----
#pragma unroll
    for (int s = 0; s < 4; ++s) {
        float d1 = b1d[s], d2 = b2d[s];
        int   i1 = b1i[s], i2 = b2i[s];
#pragma unroll
        for (int off = 1; off < 4; off <<= 1) {
            float pd1 = __shfl_xor_sync(0xFFFFFFFFu, d1, off);
            int   pi1 = __shfl_xor_sync(0xFFFFFFFFu, i1, off);
            float pd2 = __shfl_xor_sync(0xFFFFFFFFu, d2, off);
            int   pi2 = __shfl_xor_sync(0xFFFFFFFFu, i2, off);
            if (betterf(pd1, pi1, d1, i1)) {
                if (betterf(d1, i1, pd2, pi2)) { d2 = d1; i2 = i1; }
                else                           { d2 = pd2; i2 = pi2; }
                d1 = pd1; i1 = pi1;
            } else if (betterf(pd1, pi1, d2, i2)) {
                d2 = pd1; i2 = pi1;
            }
        }
        if (tig == 0) {
            const int row = wm * 32 + (s >> 1) * 16 + (s & 1) * 8 + gid;
            sd1[wn * 128 + row] = d1;  si1[wn * 128 + row] = i1;
            sd2[wn * 128 + row] = d2;  si2[wn * 128 + row] = i2;
        }
    }
    __syncthreads();

    if (tid < 128) {
        float d1 = sd1[tid], d2 = sd2[tid];
        int   i1 = si1[tid], i2 = si2[tid];
        {
            float pd1 = sd1[128 + tid], pd2 = sd2[128 + tid];
            int   pi1 = si1[128 + tid], pi2 = si2[128 + tid];
            if (betterf(pd1, pi1, d1, i1)) {
                if (betterf(d1, i1, pd2, pi2)) { d2 = d1; i2 = i1; }
                else                           { d2 = pd2; i2 = pi2; }
                d1 = pd1; i1 = pi1;
            } else if (betterf(pd1, pi1, d2, i2)) {
                d2 = pd1; i2 = pi1;
            }
        }
        int winner = i1;
        if (d2 - d1 <= MARGIN) {
            int ia = min(i1, i2), ib = max(i1, i2);
            const float* xr = Xex + (size_t)(rowBase + tid) * D;
            float x2v = __ldg(&rn2[rowBase + tid]);
            const float* ea = Eex + (size_t)ia * D;
            const float* eb = Eex + (size_t)ib * D;
            float xea = 0.f, xeb = 0.f;
            for (int k = 0; k < D; ++k) {
                float xv = __ldg(&xr[k]);
                xea = __fmaf_rn(xv, __ldg(&ea[k]), xea);
                xeb = __fmaf_rn(xv, __ldg(&eb[k]), xeb);
            }
            float da = __fmaf_rn(-2.f, xea, __fadd_rn(x2v, __ldg(&en2[ia])));
            float db = __fmaf_rn(-2.f, xeb, __fadd_rn(x2v, __ldg(&en2[ib])));
            winner = (db < da) ? ib : ia;
        }
        outIdx[rowBase + tid] = winner;
    }
}

// ---------------------------------------------------------------------------
// Fused: R = X - E[idx] (exact fp32) + write R + write packed R + ||R||^2.
// ---------------------------------------------------------------------------
__global__ void residpack_kernel(const float* __restrict__ X, const float* __restrict__ E,
                                 const int* __restrict__ idx,
                                 float* __restrict__ R, uint32_t* __restrict__ Rpk,
                                 float* __restrict__ r2)
{
    int row = blockIdx.x;
    int t   = threadIdx.x;     // 0..127
    int c   = idx[row];
    float4 xv = ((const float4*)(X + (size_t)row * D))[t];
    float4 ev = ((const float4*)(E + (size_t)c   * D))[t];
    float4 rv = make_float4(xv.x - ev.x, xv.y - ev.y, xv.z - ev.z, xv.w - ev.w);
    ((float4*)(R + (size_t)row * D))[t] = rv;

    {
        uint32_t* dst = Rpk + (size_t)row * WPR;
        int blk = t >> 2;
        int a   = t & 3;
        uint32_t whi0 = bf16pack(rv.x, rv.y);
        uint32_t wmi0 = bf16pack(rv.x - bf16round(rv.x), rv.y - bf16round(rv.y));
        uint32_t whi1 = bf16pack(rv.z, rv.w);
        uint32_t wmi1 = bf16pack(rv.z - bf16round(rv.z), rv.w - bf16round(rv.w));
        int w0 = (a < 2) ? 8 * a     : 8 * (a - 2) + 2;
        int w1 = (a < 2) ? 8 * a + 4 : 8 * (a - 2) + 6;
        dst[blk * 16 + w0]     = whi0;
        dst[blk * 16 + w0 + 1] = wmi0;
        dst[blk * 16 + w1]     = whi1;
        dst[blk * 16 + w1 + 1] = wmi1;
    }

    float s = rv.x * rv.x + rv.y * rv.y + rv.z * rv.z + rv.w * rv.w;
#pragma unroll
    for (int o = 16; o; o >>= 1) s += __shfl_down_sync(0xFFFFFFFFu, s, o);
    __shared__ float red[4];
    if ((t & 31) == 0) red[t >> 5] = s;
    __syncthreads();
    if (t == 0) r2[row] = red[0] + red[1] + red[2] + red[3];
}

// ---------------------------------------------------------------------------
// Output: out = fl(x + fl(fl(e0+e1) - x))  (reference STE rounding)
// ---------------------------------------------------------------------------
__global__ void out_kernel(const float* __restrict__ X, const float* __restrict__ E0,
                           const float* __restrict__ E1, const int* __restrict__ i0,
                           const int* __restrict__ i1, float* __restrict__ out)
{
    int row = blockIdx.x;
    int t   = threadIdx.x;
    int c0  = i0[row];
    int c1  = i1[row];
    float4 xv = ((const float4*)(X  + (size_t)row * D))[t];
    float4 a  = ((const float4*)(E0 + (size_t)c0  * D))[t];
    float4 b  = ((const float4*)(E1 + (size_t)c1  * D))[t];
    float4 o;
    o.x = __fadd_rn(xv.x, __fadd_rn(__fadd_rn(a.x, b.x), -xv.x));
    o.y = __fadd_rn(xv.y, __fadd_rn(__fadd_rn(a.y, b.y), -xv.y));
    o.z = __fadd_rn(xv.z, __fadd_rn(__fadd_rn(a.z, b.z), -xv.z));
    o.w = __fadd_rn(xv.w, __fadd_rn(__fadd_rn(a.w, b.w), -xv.w));
    ((float4*)(out + (size_t)row * D))[t] = o;
}

// ---------------------------------------------------------------------------
extern "C" void kernel_launch(void* const* d_in, const int* in_sizes, int n_in,
                              void* d_out, int out_size)
{
    const float* x  = (const float*)d_in[0];
    const float* e0 = (const float*)d_in[1];
    const float* e1 = (const float*)d_in[2];
    float* out = (float*)d_out;

    int rows = in_sizes[0] / D;   // 32768
    int nc   = in_sizes[1] / D;   // 1024

    uint32_t *papk, *pe0pk, *pe1pk;
    float *pres, *px2, *pr2, *pe2a, *pe2b;
    int   *pi0, *pi1;
    cudaGetSymbolAddress((void**)&papk,  g_apk);
    cudaGetSymbolAddress((void**)&pe0pk, g_e0pk);
    cudaGetSymbolAddress((void**)&pe1pk, g_e1pk);
    cudaGetSymbolAddress((void**)&pres,  g_res);
    cudaGetSymbolAddress((void**)&px2,   g_x2);
    cudaGetSymbolAddress((void**)&pr2,   g_r2);
    cudaGetSymbolAddress((void**)&pe2a,  g_e2a);
    cudaGetSymbolAddress((void**)&pe2b,  g_e2b);
    cudaGetSymbolAddress((void**)&pi0,   g_idx0);
    cudaGetSymbolAddress((void**)&pi1,   g_idx1);

    cudaFuncSetAttribute(stage_mma_kernel,
                         cudaFuncAttributeMaxDynamicSharedMemorySize, SMEM_DYN);

    // launch order keeps stage_mma_kernel at capture index 3
    pack_kernel<<<(rows * 32 + 255) / 256, 256>>>(x, papk, rows);
    pack2_kernel<<<(nc * 64 + 255) / 256, 256>>>(e0, e1, pe0pk, pe1pk, nc);
    norm3_kernel<<<(rows + 2 * nc + 7) / 8, 256>>>(x, px2, e0, pe2a, e1, pe2b,
                                                   rows, nc);
    stage_mma_kernel<<<rows / BM, 256, SMEM_DYN>>>(papk, pe0pk, x, e0,
                                                   px2, pe2a, pi0, nc);
    residpack_kernel<<<rows, 128>>>(x, e0, pi0, pres, papk, pr2);
    stage_mma_kernel<<<rows / BM, 256, SMEM_DYN>>>(papk, pe1pk, pres, e1,
                                                   pr2, pe2b, pi1, nc);
    out_kernel<<<rows, 128>>>(x, e0, e1, pi0, pi1, out);
}